// round 5
// baseline (speedup 1.0000x reference)
#include <cuda_runtime.h>

#define BB 4
#define LL 1024
#define DM 1024
#define NHEAD 16
#define DHEAD 64
#define MROWS (BB * LL)      // 4096
#define NCOLS (3 * DM)       // 3072

// ---- scratch (static device globals; no runtime allocation) ----
__device__ float g_qkv[MROWS * NCOLS];          // 48 MB
__device__ float g_qr[BB * NHEAD * LL * DHEAD]; // 16 MB  q + r_r_bias
__device__ float g_ss[BB * NHEAD * LL * DHEAD]; // 16 MB  q + k + r_w_bias
__device__ float g_kk[BB * NHEAD * LL * DHEAD]; // 16 MB
__device__ float g_vv[BB * NHEAD * LL * DHEAD]; // 16 MB

// ============================================================
// Kernel 1: qkv = x @ W_qkv + b_qkv   (4096x3072 = 4096x1024 @ 1024x3072)
// classic 128x128x8 tile sgemm, 8x8 per thread, A transposed in smem
// ============================================================
__global__ __launch_bounds__(256, 2)
void qkv_gemm_kernel(const float* __restrict__ A,
                     const float* __restrict__ W,
                     const float* __restrict__ bias) {
    __shared__ float As[8][128];
    __shared__ float Bs[8][128];
    const int tid = threadIdx.x;
    const int tx = tid & 15;
    const int ty = tid >> 4;
    const int bm = blockIdx.y << 7;
    const int bn = blockIdx.x << 7;
    const int arow = tid >> 1, acol = (tid & 1) << 2;
    const int brow = tid >> 5, bcol = (tid & 31) << 2;

    float acc[8][8];
#pragma unroll
    for (int i = 0; i < 8; i++)
#pragma unroll
        for (int j = 0; j < 8; j++) acc[i][j] = 0.f;

    for (int kk = 0; kk < DM; kk += 8) {
        float4 a4 = *(const float4*)&A[(bm + arow) * DM + kk + acol];
        As[acol + 0][arow] = a4.x;
        As[acol + 1][arow] = a4.y;
        As[acol + 2][arow] = a4.z;
        As[acol + 3][arow] = a4.w;
        *(float4*)&Bs[brow][bcol] =
            *(const float4*)&W[(kk + brow) * NCOLS + bn + bcol];
        __syncthreads();
#pragma unroll
        for (int k = 0; k < 8; k++) {
            float ra[8], rb[8];
            *(float4*)&ra[0] = *(float4*)&As[k][(ty << 3)];
            *(float4*)&ra[4] = *(float4*)&As[k][(ty << 3) + 4];
            *(float4*)&rb[0] = *(float4*)&Bs[k][(tx << 3)];
            *(float4*)&rb[4] = *(float4*)&Bs[k][(tx << 3) + 4];
#pragma unroll
            for (int i = 0; i < 8; i++)
#pragma unroll
                for (int j = 0; j < 8; j++)
                    acc[i][j] += ra[i] * rb[j];
        }
        __syncthreads();
    }

    float bq[8];
    *(float4*)&bq[0] = *(const float4*)&bias[bn + (tx << 3)];
    *(float4*)&bq[4] = *(const float4*)&bias[bn + (tx << 3) + 4];
#pragma unroll
    for (int i = 0; i < 8; i++) {
        const int row = bm + (ty << 3) + i;
        float4 c0 = make_float4(acc[i][0] + bq[0], acc[i][1] + bq[1],
                                acc[i][2] + bq[2], acc[i][3] + bq[3]);
        float4 c1 = make_float4(acc[i][4] + bq[4], acc[i][5] + bq[5],
                                acc[i][6] + bq[6], acc[i][7] + bq[7]);
        *(float4*)&g_qkv[row * NCOLS + bn + (tx << 3)] = c0;
        *(float4*)&g_qkv[row * NCOLS + bn + (tx << 3) + 4] = c1;
    }
}

// ============================================================
// Kernel 2: split qkv into head-major QR = q+r_r, S = q+k+r_w, K, V
// ============================================================
__global__ __launch_bounds__(256)
void split_kernel(const float* __restrict__ rr, const float* __restrict__ rw) {
    const int idx = blockIdx.x * 256 + threadIdx.x;   // < 4*1024*16*64
    const int d = idx & 63;
    const int n = (idx >> 6) & 15;
    const int l = (idx >> 10) & 1023;
    const int b = idx >> 20;
    const int src = (b * LL + l) * NCOLS + n * DHEAD + d;
    const float qv = g_qkv[src];
    const float kv = g_qkv[src + DM];
    const float vv = g_qkv[src + 2 * DM];
    const int dst = ((b * NHEAD + n) * LL + l) * DHEAD + d;
    const float rrv = rr[n * DHEAD + d];
    const float rwv = rw[n * DHEAD + d];
    g_qr[dst] = qv + rrv;
    g_ss[dst] = qv + kv + rwv;
    g_kk[dst] = kv;
    g_vv[dst] = vv;
}

// ============================================================
// Kernel 3: fused relative attention (flash-style, fp32)
//   score(q,k) = ( QR[q]·K[k] + S[q]·pos[L+k-q] ) * 0.125
// 64q x 64k tiles, 256 threads (16x16 grid), 4x4 micro-tiles.
// ============================================================
#define VP 68   // V / score smem pitch (keeps float4 alignment, breaks 32-stride)
#define SP 68
#define SMEM_FLOATS (64*64*3 + 64*128 + 64*VP + 64*SP + 192)
#define SMEM_BYTES (SMEM_FLOATS * 4)

__global__ __launch_bounds__(256, 1)
void attn_kernel(const float* __restrict__ pos, float* __restrict__ out) {
    extern __shared__ float sm[];
    float* QRs = sm;                 // [d][q]  64x64
    float* Sss = QRs + 64 * 64;      // [d][q]  64x64
    float* Ks  = Sss + 64 * 64;      // [d][k]  64x64
    float* Ps  = Ks + 64 * 64;       // [d][li] 64x128 (127 rows used)
    float* Vs  = Ps + 64 * 128;      // [k][d]  64xVP
    float* Sc  = Vs + 64 * VP;       // [q][k]  64xSP
    float* m_run = Sc + 64 * SP;     // [64]
    float* l_run = m_run + 64;       // [64]
    float* fsc   = l_run + 64;       // [64]

    const int tid = threadIdx.x;
    const int tx = tid & 15, ty = tid >> 4;
    const int q0 = blockIdx.x << 6;
    const int n = blockIdx.y, b = blockIdx.z;
    const int bn = b * NHEAD + n;
    const float* qrg = g_qr + (size_t)bn * LL * DHEAD;
    const float* ssg = g_ss + (size_t)bn * LL * DHEAD;
    const float* kg  = g_kk + (size_t)bn * LL * DHEAD;
    const float* vg  = g_vv + (size_t)bn * LL * DHEAD;

    // load QR / S tiles transposed into [d][q] (once per block)
    for (int i = tid; i < 64 * 16; i += 256) {
        const int q = i >> 4, dq = (i & 15) << 2;
        float4 a = *(const float4*)&qrg[(q0 + q) * DHEAD + dq];
        QRs[(dq + 0) * 64 + q] = a.x; QRs[(dq + 1) * 64 + q] = a.y;
        QRs[(dq + 2) * 64 + q] = a.z; QRs[(dq + 3) * 64 + q] = a.w;
        float4 s = *(const float4*)&ssg[(q0 + q) * DHEAD + dq];
        Sss[(dq + 0) * 64 + q] = s.x; Sss[(dq + 1) * 64 + q] = s.y;
        Sss[(dq + 2) * 64 + q] = s.z; Sss[(dq + 3) * 64 + q] = s.w;
    }
    if (tid < 64) { m_run[tid] = -1e30f; l_run[tid] = 0.f; }

    float o[4][4];
#pragma unroll
    for (int i = 0; i < 4; i++)
#pragma unroll
        for (int j = 0; j < 4; j++) o[i][j] = 0.f;

    // per-thread base into the 127-row diagonal pos slice: li = 63 + k - q
    const int pd = 60 + ((tx - ty) << 2);   // in [0,120], float4-aligned

    for (int kt = 0; kt < 16; kt++) {
        const int k0 = kt << 6;
        const int pbase = LL + k0 - q0 - 63;  // in [1, 2047-126]

        // load K transposed [d][k], V natural [k][d]
        for (int i = tid; i < 64 * 16; i += 256) {
            const int kr = i >> 4, dq = (i & 15) << 2;
            float4 a = *(const float4*)&kg[(k0 + kr) * DHEAD + dq];
            Ks[(dq + 0) * 64 + kr] = a.x; Ks[(dq + 1) * 64 + kr] = a.y;
            Ks[(dq + 2) * 64 + kr] = a.z; Ks[(dq + 3) * 64 + kr] = a.w;
            *(float4*)&Vs[kr * VP + dq] =
                *(const float4*)&vg[(k0 + kr) * DHEAD + dq];
        }
        // load 127 pos rows transposed [d][li]
        for (int i = tid; i < 127 * 16; i += 256) {
            const int li = i >> 4, dq = (i & 15) << 2;
            float4 a = *(const float4*)&pos[(pbase + li) * DHEAD + dq];
            Ps[(dq + 0) * 128 + li] = a.x; Ps[(dq + 1) * 128 + li] = a.y;
            Ps[(dq + 2) * 128 + li] = a.z; Ps[(dq + 3) * 128 + li] = a.w;
        }
        __syncthreads();

        // ---- score tile: AC + BDE ----
        float acc[4][4];
#pragma unroll
        for (int i = 0; i < 4; i++)
#pragma unroll
            for (int j = 0; j < 4; j++) acc[i][j] = 0.f;

#pragma unroll 4
        for (int d = 0; d < 64; d++) {
            float4 q4 = *(float4*)&QRs[d * 64 + (ty << 2)];
            float4 k4 = *(float4*)&Ks[d * 64 + (tx << 2)];
            float4 s4 = *(float4*)&Sss[d * 64 + (ty << 2)];
            float4 p0 = *(float4*)&Ps[d * 128 + pd];
            float4 p1 = *(float4*)&Ps[d * 128 + pd + 4];
            float qa[4] = {q4.x, q4.y, q4.z, q4.w};
            float ka[4] = {k4.x, k4.y, k4.z, k4.w};
            float sa[4] = {s4.x, s4.y, s4.z, s4.w};
            float pb[8] = {p0.x, p0.y, p0.z, p0.w, p1.x, p1.y, p1.z, p1.w};
#pragma unroll
            for (int ri = 0; ri < 4; ri++)
#pragma unroll
                for (int ci = 0; ci < 4; ci++)
                    acc[ri][ci] += qa[ri] * ka[ci] + sa[ri] * pb[3 + ci - ri];
        }
#pragma unroll
        for (int ri = 0; ri < 4; ri++)
            *(float4*)&Sc[((ty << 2) + ri) * SP + (tx << 2)] =
                make_float4(acc[ri][0], acc[ri][1], acc[ri][2], acc[ri][3]);
        __syncthreads();

        // ---- online softmax (4 threads per row; quad = 4 warp lanes) ----
        {
            const int row = tid >> 2, sub = tid & 3;
            float* p = &Sc[row * SP + (sub << 4)];
            float v[16];
            float4 v0 = *(float4*)&p[0], v1 = *(float4*)&p[4];
            float4 v2 = *(float4*)&p[8], v3 = *(float4*)&p[12];
            v[0]=v0.x*0.125f; v[1]=v0.y*0.125f; v[2]=v0.z*0.125f; v[3]=v0.w*0.125f;
            v[4]=v1.x*0.125f; v[5]=v1.y*0.125f; v[6]=v1.z*0.125f; v[7]=v1.w*0.125f;
            v[8]=v2.x*0.125f; v[9]=v2.y*0.125f; v[10]=v2.z*0.125f; v[11]=v2.w*0.125f;
            v[12]=v3.x*0.125f; v[13]=v3.y*0.125f; v[14]=v3.z*0.125f; v[15]=v3.w*0.125f;
            float mx = v[0];
#pragma unroll
            for (int j = 1; j < 16; j++) mx = fmaxf(mx, v[j]);
            mx = fmaxf(mx, __shfl_xor_sync(0xffffffffu, mx, 1));
            mx = fmaxf(mx, __shfl_xor_sync(0xffffffffu, mx, 2));
            const float mold = m_run[row];
            const float mnew = fmaxf(mold, mx);
            const float fac = __expf(mold - mnew);
            float s = 0.f;
#pragma unroll
            for (int j = 0; j < 16; j++) { v[j] = __expf(v[j] - mnew); s += v[j]; }
            *(float4*)&p[0]  = make_float4(v[0],  v[1],  v[2],  v[3]);
            *(float4*)&p[4]  = make_float4(v[4],  v[5],  v[6],  v[7]);
            *(float4*)&p[8]  = make_float4(v[8],  v[9],  v[10], v[11]);
            *(float4*)&p[12] = make_float4(v[12], v[13], v[14], v[15]);
            s += __shfl_xor_sync(0xffffffffu, s, 1);
            s += __shfl_xor_sync(0xffffffffu, s, 2);
            if (sub == 0) {
                l_run[row] = l_run[row] * fac + s;
                m_run[row] = mnew;
                fsc[row] = fac;
            }
        }
        __syncthreads();

        // ---- O rescale + PV accumulate ----
#pragma unroll
        for (int ri = 0; ri < 4; ri++) {
            const float f = fsc[(ty << 2) + ri];
#pragma unroll
            for (int ci = 0; ci < 4; ci++) o[ri][ci] *= f;
        }
#pragma unroll 8
        for (int k = 0; k < 64; k++) {
            const float a0 = Sc[((ty << 2) + 0) * SP + k];
            const float a1 = Sc[((ty << 2) + 1) * SP + k];
            const float a2 = Sc[((ty << 2) + 2) * SP + k];
            const float a3 = Sc[((ty << 2) + 3) * SP + k];
            float4 v4 = *(float4*)&Vs[k * VP + (tx << 2)];
            o[0][0] += a0 * v4.x; o[0][1] += a0 * v4.y; o[0][2] += a0 * v4.z; o[0][3] += a0 * v4.w;
            o[1][0] += a1 * v4.x; o[1][1] += a1 * v4.y; o[1][2] += a1 * v4.z; o[1][3] += a1 * v4.w;
            o[2][0] += a2 * v4.x; o[2][1] += a2 * v4.y; o[2][2] += a2 * v4.z; o[2][3] += a2 * v4.w;
            o[3][0] += a3 * v4.x; o[3][1] += a3 * v4.y; o[3][2] += a3 * v4.z; o[3][3] += a3 * v4.w;
        }
        __syncthreads();
    }

    // finalize: out[b, q, n*64 + d]
#pragma unroll
    for (int ri = 0; ri < 4; ri++) {
        const int q = q0 + (ty << 2) + ri;
        const float inv = 1.0f / l_run[(ty << 2) + ri];
        float4 r = make_float4(o[ri][0] * inv, o[ri][1] * inv,
                               o[ri][2] * inv, o[ri][3] * inv);
        *(float4*)&out[((size_t)(b * LL + q)) * DM + n * DHEAD + (tx << 2)] = r;
    }
}

// ============================================================
extern "C" void kernel_launch(void* const* d_in, const int* in_sizes, int n_in,
                              void* d_out, int out_size) {
    const float* x   = (const float*)d_in[0];
    const float* pos = (const float*)d_in[1];
    const float* W   = (const float*)d_in[2];
    const float* bqk = (const float*)d_in[3];
    const float* rr  = (const float*)d_in[4];
    const float* rw  = (const float*)d_in[5];
    float* out = (float*)d_out;

    cudaFuncSetAttribute(attn_kernel,
                         cudaFuncAttributeMaxDynamicSharedMemorySize, SMEM_BYTES);

    qkv_gemm_kernel<<<dim3(NCOLS / 128, MROWS / 128), 256>>>(x, W, bqk);
    split_kernel<<<(BB * LL * NHEAD * DHEAD) / 256, 256>>>(rr, rw);
    attn_kernel<<<dim3(LL / 64, NHEAD, BB), 256, SMEM_BYTES>>>(pos, out);
}

// round 9
// speedup vs baseline: 1.2583x; 1.2583x over previous
#include <cuda_runtime.h>
#include <cuda_bf16.h>
#include <cstdint>

#define BB 4
#define LL 1024
#define DM 1024
#define NHEAD 16
#define DHEAD 64
#define MROWS (BB * LL)      // 4096
#define NCOLS (3 * DM)       // 3072

// ---- scratch (static device globals; no runtime allocation) ----
__device__ float g_qkv[MROWS * NCOLS];          // 48 MB
__device__ float g_qr[BB * NHEAD * LL * DHEAD]; // 16 MB  q + r_r_bias
__device__ float g_ss[BB * NHEAD * LL * DHEAD]; // 16 MB  q + k + r_w_bias
__device__ float g_kk[BB * NHEAD * LL * DHEAD]; // 16 MB
__device__ float g_vv[BB * NHEAD * LL * DHEAD]; // 16 MB
// bf16 split operands for mma.sync qkv GEMM
__device__ __nv_bfloat16 g_a_hi[MROWS * DM];    // 8 MB
__device__ __nv_bfloat16 g_a_lo[MROWS * DM];
__device__ __nv_bfloat16 g_wt_hi[NCOLS * DM];   // 6 MB (W transposed: [n][k])
__device__ __nv_bfloat16 g_wt_lo[NCOLS * DM];

// ============================================================
// helpers
// ============================================================
__device__ __forceinline__ uint32_t smem_to_u32(const void* p) {
    uint32_t a;
    asm("{ .reg .u64 t; cvta.to.shared.u64 t, %1; cvt.u32.u64 %0, t; }"
        : "=r"(a) : "l"(p));
    return a;
}
#define SMEM_SWIZZLE_128B(byte_offset) \
    ((byte_offset) ^ (((byte_offset) >> 3) & 0x70))

__device__ __forceinline__ void ldsm4(uint32_t* r, uint32_t addr) {
    asm volatile("ldmatrix.sync.aligned.m8n8.x4.shared.b16 {%0,%1,%2,%3}, [%4];"
        : "=r"(r[0]), "=r"(r[1]), "=r"(r[2]), "=r"(r[3]) : "r"(addr));
}
__device__ __forceinline__ void mma16816(float* c, const uint32_t* a, const uint32_t* b) {
    asm volatile(
        "mma.sync.aligned.m16n8k16.row.col.f32.bf16.bf16.f32 "
        "{%0,%1,%2,%3}, {%4,%5,%6,%7}, {%8,%9}, {%0,%1,%2,%3};"
        : "+f"(c[0]), "+f"(c[1]), "+f"(c[2]), "+f"(c[3])
        : "r"(a[0]), "r"(a[1]), "r"(a[2]), "r"(a[3]), "r"(b[0]), "r"(b[1]));
}

// ============================================================
// Conversion kernels: fp32 -> bf16 hi/lo split
// ============================================================
__global__ __launch_bounds__(256)
void conv_x_kernel(const float* __restrict__ x) {
    const int i = blockIdx.x * 256 + threadIdx.x;   // < 4096*1024
    const float v = x[i];
    const __nv_bfloat16 h = __float2bfloat16(v);
    const float r = v - __bfloat162float(h);
    g_a_hi[i] = h;
    g_a_lo[i] = __float2bfloat16(r);
}

// W[k][n] (1024 x 3072) -> Wt[n][k] (3072 x 1024), bf16 hi/lo
__global__ __launch_bounds__(256)
void conv_w_kernel(const float* __restrict__ W) {
    __shared__ float t[32][33];
    const int tx = threadIdx.x, ty = threadIdx.y;   // (32, 8)
    const int n0 = blockIdx.x * 32, k0 = blockIdx.y * 32;
#pragma unroll
    for (int i = 0; i < 4; i++)
        t[ty + i * 8][tx] = W[(k0 + ty + i * 8) * NCOLS + n0 + tx];
    __syncthreads();
#pragma unroll
    for (int i = 0; i < 4; i++) {
        const int n = n0 + ty + i * 8;
        const int k = k0 + tx;
        const float v = t[tx][ty + i * 8];
        const __nv_bfloat16 h = __float2bfloat16(v);
        const float r = v - __bfloat162float(h);
        g_wt_hi[n * DM + k] = h;
        g_wt_lo[n * DM + k] = __float2bfloat16(r);
    }
}

// ============================================================
// Kernel 1: qkv = x @ W_qkv + b_qkv via mma.sync bf16 2-term split
// CTA tile 128x128, K in 16 chunks of 64; 8 warps = 2(M) x 4(N),
// each warp: 4x4 m16n8k16 tiles, acc fp32.
// D = Ahi*Bhi + Alo*Bhi + Ahi*Blo
// smem: AH 16K | AL 16K | BH 16K | BL 16K  (single buffer, occ=2)
// ============================================================
#define QK_SMEM_TOTAL 65536

__global__ __launch_bounds__(256, 2)
void qkv_tc_kernel(const float* __restrict__ bias) {
    extern __shared__ char smem[];
    const uint32_t sb = smem_to_u32(smem);
    const int tid = threadIdx.x;
    const int lane = tid & 31, wid = tid >> 5;
    const int n0 = blockIdx.x << 7, m0 = blockIdx.y << 7;
    const int mw = (wid & 1) << 6;      // warp M offset: 0 / 64
    const int nw = (wid >> 1) << 5;     // warp N offset: 0/32/64/96

    float acc[4][4][4];
#pragma unroll
    for (int a = 0; a < 4; a++)
#pragma unroll
        for (int b = 0; b < 4; b++)
#pragma unroll
            for (int c = 0; c < 4; c++) acc[a][b][c] = 0.f;

    // per-lane ldmatrix pre-swizzle coords
    // A x4: matrices (r0-7,k0-7),(r8-15,k0-7),(r0-7,k8-15),(r8-15,k8-15)
    const int a_r  = mw + (lane & 15);
    const int a_cb = (lane >> 4) << 4;          // 0 / 16 bytes
    // B x4: matrices (n0-7,k0-7),(n0-7,k8-15),(n8-15,k0-7),(n8-15,k8-15)
    const int b_r  = nw + (lane & 7) + ((lane >> 4) << 3);
    const int b_cb = (lane & 8) << 1;           // 0 / 16 bytes

    for (int chunk = 0; chunk < 16; chunk++) {
        const int kk = chunk << 6;
#pragma unroll
        for (int j = 0; j < 4; j++) {
            const int t = tid + j * 256;        // 0..1023
            const int r = t >> 3, g = t & 7;    // row, 16B group
            const uint32_t sw = SMEM_SWIZZLE_128B((uint32_t)(r * 128 + g * 16));
            const size_t asrc = (size_t)(m0 + r) * DM + kk + g * 8;
            const size_t bsrc = (size_t)(n0 + r) * DM + kk + g * 8;
            *(uint4*)(smem + sw)         = *(const uint4*)&g_a_hi[asrc];
            *(uint4*)(smem + 16384 + sw) = *(const uint4*)&g_a_lo[asrc];
            *(uint4*)(smem + 32768 + sw) = *(const uint4*)&g_wt_hi[bsrc];
            *(uint4*)(smem + 49152 + sw) = *(const uint4*)&g_wt_lo[bsrc];
        }
        __syncthreads();

#pragma unroll
        for (int ks = 0; ks < 4; ks++) {
            const int cb = ks << 5;             // 32 bytes per k16 step
            uint32_t ah[4][4], bb[2][4];
#pragma unroll
            for (int mt = 0; mt < 4; mt++)
                ldsm4(ah[mt], sb + SMEM_SWIZZLE_128B(
                    (uint32_t)((a_r + mt * 16) * 128 + cb + a_cb)));
#pragma unroll
            for (int p = 0; p < 2; p++)
                ldsm4(bb[p], sb + 32768 + SMEM_SWIZZLE_128B(
                    (uint32_t)((b_r + p * 16) * 128 + cb + b_cb)));
            // hi * hi
#pragma unroll
            for (int mt = 0; mt < 4; mt++)
#pragma unroll
                for (int j = 0; j < 4; j++)
                    mma16816(acc[mt][j], ah[mt], &bb[j >> 1][(j & 1) * 2]);
            // lo * hi  (B hi still resident)
            {
                uint32_t al[4][4];
#pragma unroll
                for (int mt = 0; mt < 4; mt++)
                    ldsm4(al[mt], sb + 16384 + SMEM_SWIZZLE_128B(
                        (uint32_t)((a_r + mt * 16) * 128 + cb + a_cb)));
#pragma unroll
                for (int mt = 0; mt < 4; mt++)
#pragma unroll
                    for (int j = 0; j < 4; j++)
                        mma16816(acc[mt][j], al[mt], &bb[j >> 1][(j & 1) * 2]);
            }
            // hi * lo  (replace B with lo)
#pragma unroll
            for (int p = 0; p < 2; p++)
                ldsm4(bb[p], sb + 49152 + SMEM_SWIZZLE_128B(
                    (uint32_t)((b_r + p * 16) * 128 + cb + b_cb)));
#pragma unroll
            for (int mt = 0; mt < 4; mt++)
#pragma unroll
                for (int j = 0; j < 4; j++)
                    mma16816(acc[mt][j], ah[mt], &bb[j >> 1][(j & 1) * 2]);
        }
        __syncthreads();
    }

    // epilogue: c0,c1 -> (row, col..col+1); c2,c3 -> (row+8, ...)
    const int er = lane >> 2, ec = (lane & 3) << 1;
#pragma unroll
    for (int mt = 0; mt < 4; mt++) {
#pragma unroll
        for (int j = 0; j < 4; j++) {
            const int row = m0 + mw + mt * 16 + er;
            const int col = n0 + nw + j * 8 + ec;
            const float2 bv = *(const float2*)&bias[col];
            float2 lo = make_float2(acc[mt][j][0] + bv.x, acc[mt][j][1] + bv.y);
            float2 hi = make_float2(acc[mt][j][2] + bv.x, acc[mt][j][3] + bv.y);
            *(float2*)&g_qkv[(size_t)row * NCOLS + col] = lo;
            *(float2*)&g_qkv[(size_t)(row + 8) * NCOLS + col] = hi;
        }
    }
}

// ============================================================
// Kernel 2: split qkv into head-major QR = q+r_r, S = q+k+r_w, K, V
// ============================================================
__global__ __launch_bounds__(256)
void split_kernel(const float* __restrict__ rr, const float* __restrict__ rw) {
    const int idx = blockIdx.x * 256 + threadIdx.x;   // < 4*1024*16*64
    const int d = idx & 63;
    const int n = (idx >> 6) & 15;
    const int l = (idx >> 10) & 1023;
    const int b = idx >> 20;
    const int src = (b * LL + l) * NCOLS + n * DHEAD + d;
    const float qv = g_qkv[src];
    const float kv = g_qkv[src + DM];
    const float vv = g_qkv[src + 2 * DM];
    const int dst = ((b * NHEAD + n) * LL + l) * DHEAD + d;
    const float rrv = rr[n * DHEAD + d];
    const float rwv = rw[n * DHEAD + d];
    g_qr[dst] = qv + rrv;
    g_ss[dst] = qv + kv + rwv;
    g_kk[dst] = kv;
    g_vv[dst] = vv;
}

// ============================================================
// Kernel 3: fused relative attention (flash-style, fp32)  [unchanged]
//   score(q,k) = ( QR[q]·K[k] + S[q]·pos[L+k-q] ) * 0.125
// ============================================================
#define VP 68
#define SP 68
#define SMEM_FLOATS (64*64*3 + 64*128 + 64*VP + 64*SP + 192)
#define SMEM_BYTES (SMEM_FLOATS * 4)

__global__ __launch_bounds__(256, 1)
void attn_kernel(const float* __restrict__ pos, float* __restrict__ out) {
    extern __shared__ float sm[];
    float* QRs = sm;
    float* Sss = QRs + 64 * 64;
    float* Ks  = Sss + 64 * 64;
    float* Ps  = Ks + 64 * 64;
    float* Vs  = Ps + 64 * 128;
    float* Sc  = Vs + 64 * VP;
    float* m_run = Sc + 64 * SP;
    float* l_run = m_run + 64;
    float* fsc   = l_run + 64;

    const int tid = threadIdx.x;
    const int tx = tid & 15, ty = tid >> 4;
    const int q0 = blockIdx.x << 6;
    const int n = blockIdx.y, b = blockIdx.z;
    const int bn = b * NHEAD + n;
    const float* qrg = g_qr + (size_t)bn * LL * DHEAD;
    const float* ssg = g_ss + (size_t)bn * LL * DHEAD;
    const float* kg  = g_kk + (size_t)bn * LL * DHEAD;
    const float* vg  = g_vv + (size_t)bn * LL * DHEAD;

    for (int i = tid; i < 64 * 16; i += 256) {
        const int q = i >> 4, dq = (i & 15) << 2;
        float4 a = *(const float4*)&qrg[(q0 + q) * DHEAD + dq];
        QRs[(dq + 0) * 64 + q] = a.x; QRs[(dq + 1) * 64 + q] = a.y;
        QRs[(dq + 2) * 64 + q] = a.z; QRs[(dq + 3) * 64 + q] = a.w;
        float4 s = *(const float4*)&ssg[(q0 + q) * DHEAD + dq];
        Sss[(dq + 0) * 64 + q] = s.x; Sss[(dq + 1) * 64 + q] = s.y;
        Sss[(dq + 2) * 64 + q] = s.z; Sss[(dq + 3) * 64 + q] = s.w;
    }
    if (tid < 64) { m_run[tid] = -1e30f; l_run[tid] = 0.f; }

    float o[4][4];
#pragma unroll
    for (int i = 0; i < 4; i++)
#pragma unroll
        for (int j = 0; j < 4; j++) o[i][j] = 0.f;

    const int pd = 60 + ((tx - ty) << 2);

    for (int kt = 0; kt < 16; kt++) {
        const int k0 = kt << 6;
        const int pbase = LL + k0 - q0 - 63;

        for (int i = tid; i < 64 * 16; i += 256) {
            const int kr = i >> 4, dq = (i & 15) << 2;
            float4 a = *(const float4*)&kg[(k0 + kr) * DHEAD + dq];
            Ks[(dq + 0) * 64 + kr] = a.x; Ks[(dq + 1) * 64 + kr] = a.y;
            Ks[(dq + 2) * 64 + kr] = a.z; Ks[(dq + 3) * 64 + kr] = a.w;
            *(float4*)&Vs[kr * VP + dq] =
                *(const float4*)&vg[(k0 + kr) * DHEAD + dq];
        }
        for (int i = tid; i < 127 * 16; i += 256) {
            const int li = i >> 4, dq = (i & 15) << 2;
            float4 a = *(const float4*)&pos[(pbase + li) * DHEAD + dq];
            Ps[(dq + 0) * 128 + li] = a.x; Ps[(dq + 1) * 128 + li] = a.y;
            Ps[(dq + 2) * 128 + li] = a.z; Ps[(dq + 3) * 128 + li] = a.w;
        }
        __syncthreads();

        float acc[4][4];
#pragma unroll
        for (int i = 0; i < 4; i++)
#pragma unroll
            for (int j = 0; j < 4; j++) acc[i][j] = 0.f;

#pragma unroll 4
        for (int d = 0; d < 64; d++) {
            float4 q4 = *(float4*)&QRs[d * 64 + (ty << 2)];
            float4 k4 = *(float4*)&Ks[d * 64 + (tx << 2)];
            float4 s4 = *(float4*)&Sss[d * 64 + (ty << 2)];
            float4 p0 = *(float4*)&Ps[d * 128 + pd];
            float4 p1 = *(float4*)&Ps[d * 128 + pd + 4];
            float qa[4] = {q4.x, q4.y, q4.z, q4.w};
            float ka[4] = {k4.x, k4.y, k4.z, k4.w};
            float sa[4] = {s4.x, s4.y, s4.z, s4.w};
            float pb[8] = {p0.x, p0.y, p0.z, p0.w, p1.x, p1.y, p1.z, p1.w};
#pragma unroll
            for (int ri = 0; ri < 4; ri++)
#pragma unroll
                for (int ci = 0; ci < 4; ci++)
                    acc[ri][ci] += qa[ri] * ka[ci] + sa[ri] * pb[3 + ci - ri];
        }
#pragma unroll
        for (int ri = 0; ri < 4; ri++)
            *(float4*)&Sc[((ty << 2) + ri) * SP + (tx << 2)] =
                make_float4(acc[ri][0], acc[ri][1], acc[ri][2], acc[ri][3]);
        __syncthreads();

        {
            const int row = tid >> 2, sub = tid & 3;
            float* p = &Sc[row * SP + (sub << 4)];
            float v[16];
            float4 v0 = *(float4*)&p[0], v1 = *(float4*)&p[4];
            float4 v2 = *(float4*)&p[8], v3 = *(float4*)&p[12];
            v[0]=v0.x*0.125f; v[1]=v0.y*0.125f; v[2]=v0.z*0.125f; v[3]=v0.w*0.125f;
            v[4]=v1.x*0.125f; v[5]=v1.y*0.125f; v[6]=v1.z*0.125f; v[7]=v1.w*0.125f;
            v[8]=v2.x*0.125f; v[9]=v2.y*0.125f; v[10]=v2.z*0.125f; v[11]=v2.w*0.125f;
            v[12]=v3.x*0.125f; v[13]=v3.y*0.125f; v[14]=v3.z*0.125f; v[15]=v3.w*0.125f;
            float mx = v[0];
#pragma unroll
            for (int j = 1; j < 16; j++) mx = fmaxf(mx, v[j]);
            mx = fmaxf(mx, __shfl_xor_sync(0xffffffffu, mx, 1));
            mx = fmaxf(mx, __shfl_xor_sync(0xffffffffu, mx, 2));
            const float mold = m_run[row];
            const float mnew = fmaxf(mold, mx);
            const float fac = __expf(mold - mnew);
            float s = 0.f;
#pragma unroll
            for (int j = 0; j < 16; j++) { v[j] = __expf(v[j] - mnew); s += v[j]; }
            *(float4*)&p[0]  = make_float4(v[0],  v[1],  v[2],  v[3]);
            *(float4*)&p[4]  = make_float4(v[4],  v[5],  v[6],  v[7]);
            *(float4*)&p[8]  = make_float4(v[8],  v[9],  v[10], v[11]);
            *(float4*)&p[12] = make_float4(v[12], v[13], v[14], v[15]);
            s += __shfl_xor_sync(0xffffffffu, s, 1);
            s += __shfl_xor_sync(0xffffffffu, s, 2);
            if (sub == 0) {
                l_run[row] = l_run[row] * fac + s;
                m_run[row] = mnew;
                fsc[row] = fac;
            }
        }
        __syncthreads();

#pragma unroll
        for (int ri = 0; ri < 4; ri++) {
            const float f = fsc[(ty << 2) + ri];
#pragma unroll
            for (int ci = 0; ci < 4; ci++) o[ri][ci] *= f;
        }
#pragma unroll 8
        for (int k = 0; k < 64; k++) {
            const float a0 = Sc[((ty << 2) + 0) * SP + k];
            const float a1 = Sc[((ty << 2) + 1) * SP + k];
            const float a2 = Sc[((ty << 2) + 2) * SP + k];
            const float a3 = Sc[((ty << 2) + 3) * SP + k];
            float4 v4 = *(float4*)&Vs[k * VP + (tx << 2)];
            o[0][0] += a0 * v4.x; o[0][1] += a0 * v4.y; o[0][2] += a0 * v4.z; o[0][3] += a0 * v4.w;
            o[1][0] += a1 * v4.x; o[1][1] += a1 * v4.y; o[1][2] += a1 * v4.z; o[1][3] += a1 * v4.w;
            o[2][0] += a2 * v4.x; o[2][1] += a2 * v4.y; o[2][2] += a2 * v4.z; o[2][3] += a2 * v4.w;
            o[3][0] += a3 * v4.x; o[3][1] += a3 * v4.y; o[3][2] += a3 * v4.z; o[3][3] += a3 * v4.w;
        }
        __syncthreads();
    }

#pragma unroll
    for (int ri = 0; ri < 4; ri++) {
        const int q = q0 + (ty << 2) + ri;
        const float inv = 1.0f / l_run[(ty << 2) + ri];
        float4 r = make_float4(o[ri][0] * inv, o[ri][1] * inv,
                               o[ri][2] * inv, o[ri][3] * inv);
        *(float4*)&out[((size_t)(b * LL + q)) * DM + n * DHEAD + (tx << 2)] = r;
    }
}

// ============================================================
extern "C" void kernel_launch(void* const* d_in, const int* in_sizes, int n_in,
                              void* d_out, int out_size) {
    const float* x   = (const float*)d_in[0];
    const float* pos = (const float*)d_in[1];
    const float* W   = (const float*)d_in[2];
    const float* bqk = (const float*)d_in[3];
    const float* rr  = (const float*)d_in[4];
    const float* rw  = (const float*)d_in[5];
    float* out = (float*)d_out;

    cudaFuncSetAttribute(attn_kernel,
                         cudaFuncAttributeMaxDynamicSharedMemorySize, SMEM_BYTES);
    cudaFuncSetAttribute(qkv_tc_kernel,
                         cudaFuncAttributeMaxDynamicSharedMemorySize, QK_SMEM_TOTAL);

    conv_x_kernel<<<(MROWS * DM) / 256, 256>>>(x);
    conv_w_kernel<<<dim3(NCOLS / 32, DM / 32), dim3(32, 8)>>>(W);
    qkv_tc_kernel<<<dim3(NCOLS / 128, MROWS / 128), 256, QK_SMEM_TOTAL>>>(bqk);
    split_kernel<<<(BB * LL * NHEAD * DHEAD) / 256, 256>>>(rr, rw);
    attn_kernel<<<dim3(LL / 64, NHEAD, BB), 256, SMEM_BYTES>>>(pos, out);
}

// round 10
// speedup vs baseline: 1.9229x; 1.5282x over previous
#include <cuda_runtime.h>
#include <cuda_bf16.h>
#include <cstdint>

#define BB 4
#define LL 1024
#define DM 1024
#define NHEAD 16
#define DHEAD 64
#define MROWS (BB * LL)      // 4096
#define NCOLS (3 * DM)       // 3072

// ---- scratch (static device globals; no runtime allocation) ----
__device__ float g_qkv[MROWS * NCOLS];          // 48 MB
__device__ float g_qr[BB * NHEAD * LL * DHEAD]; // 16 MB  q + r_r_bias
__device__ float g_ss[BB * NHEAD * LL * DHEAD]; // 16 MB  q + k + r_w_bias
__device__ float g_kk[BB * NHEAD * LL * DHEAD]; // 16 MB
__device__ float g_vv[BB * NHEAD * LL * DHEAD]; // 16 MB
// bf16 split operands for mma.sync qkv GEMM
__device__ __nv_bfloat16 g_a_hi[MROWS * DM];    // 8 MB
__device__ __nv_bfloat16 g_a_lo[MROWS * DM];
__device__ __nv_bfloat16 g_wt_hi[NCOLS * DM];   // 6 MB (W transposed: [n][k])
__device__ __nv_bfloat16 g_wt_lo[NCOLS * DM];

// ============================================================
// helpers
// ============================================================
__device__ __forceinline__ uint32_t smem_to_u32(const void* p) {
    uint32_t a;
    asm("{ .reg .u64 t; cvta.to.shared.u64 t, %1; cvt.u32.u64 %0, t; }"
        : "=r"(a) : "l"(p));
    return a;
}
#define SMEM_SWIZZLE_128B(byte_offset) \
    ((byte_offset) ^ (((byte_offset) >> 3) & 0x70))

__device__ __forceinline__ void ldsm4(uint32_t* r, uint32_t addr) {
    asm volatile("ldmatrix.sync.aligned.m8n8.x4.shared.b16 {%0,%1,%2,%3}, [%4];"
        : "=r"(r[0]), "=r"(r[1]), "=r"(r[2]), "=r"(r[3]) : "r"(addr));
}
__device__ __forceinline__ void mma16816(float* c, const uint32_t* a, const uint32_t* b) {
    asm volatile(
        "mma.sync.aligned.m16n8k16.row.col.f32.bf16.bf16.f32 "
        "{%0,%1,%2,%3}, {%4,%5,%6,%7}, {%8,%9}, {%0,%1,%2,%3};"
        : "+f"(c[0]), "+f"(c[1]), "+f"(c[2]), "+f"(c[3])
        : "r"(a[0]), "r"(a[1]), "r"(a[2]), "r"(a[3]), "r"(b[0]), "r"(b[1]));
}

// split 8 fp32 into 8 bf16 hi + 8 bf16 lo, packed as uint4 each
__device__ __forceinline__ void split8(const float* v, uint4& h4, uint4& l4) {
    uint32_t h[4], l[4];
#pragma unroll
    for (int i = 0; i < 4; i++) {
        float x = v[2 * i], y = v[2 * i + 1];
        __nv_bfloat16 hx = __float2bfloat16(x), hy = __float2bfloat16(y);
        float rx = x - __bfloat162float(hx), ry = y - __bfloat162float(hy);
        __nv_bfloat16 lx = __float2bfloat16(rx), ly = __float2bfloat16(ry);
        h[i] = (uint32_t)(*(uint16_t*)&hx) | ((uint32_t)(*(uint16_t*)&hy) << 16);
        l[i] = (uint32_t)(*(uint16_t*)&lx) | ((uint32_t)(*(uint16_t*)&ly) << 16);
    }
    h4 = make_uint4(h[0], h[1], h[2], h[3]);
    l4 = make_uint4(l[0], l[1], l[2], l[3]);
}

// ============================================================
// Conversion kernels: fp32 -> bf16 hi/lo split
// ============================================================
__global__ __launch_bounds__(256)
void conv_x_kernel(const float* __restrict__ x) {
    const int i = blockIdx.x * 256 + threadIdx.x;
    const float v = x[i];
    const __nv_bfloat16 h = __float2bfloat16(v);
    const float r = v - __bfloat162float(h);
    g_a_hi[i] = h;
    g_a_lo[i] = __float2bfloat16(r);
}

__global__ __launch_bounds__(256)
void conv_w_kernel(const float* __restrict__ W) {
    __shared__ float t[32][33];
    const int tx = threadIdx.x, ty = threadIdx.y;
    const int n0 = blockIdx.x * 32, k0 = blockIdx.y * 32;
#pragma unroll
    for (int i = 0; i < 4; i++)
        t[ty + i * 8][tx] = W[(k0 + ty + i * 8) * NCOLS + n0 + tx];
    __syncthreads();
#pragma unroll
    for (int i = 0; i < 4; i++) {
        const int n = n0 + ty + i * 8;
        const int k = k0 + tx;
        const float v = t[tx][ty + i * 8];
        const __nv_bfloat16 h = __float2bfloat16(v);
        const float r = v - __bfloat162float(h);
        g_wt_hi[n * DM + k] = h;
        g_wt_lo[n * DM + k] = __float2bfloat16(r);
    }
}

// ============================================================
// Kernel 1: qkv = x @ W_qkv + b_qkv via mma.sync bf16 2-term split
// ============================================================
#define QK_SMEM_TOTAL 65536

__global__ __launch_bounds__(256, 2)
void qkv_tc_kernel(const float* __restrict__ bias) {
    extern __shared__ char smem[];
    const uint32_t sb = smem_to_u32(smem);
    const int tid = threadIdx.x;
    const int lane = tid & 31, wid = tid >> 5;
    const int n0 = blockIdx.x << 7, m0 = blockIdx.y << 7;
    const int mw = (wid & 1) << 6;
    const int nw = (wid >> 1) << 5;

    float acc[4][4][4];
#pragma unroll
    for (int a = 0; a < 4; a++)
#pragma unroll
        for (int b = 0; b < 4; b++)
#pragma unroll
            for (int c = 0; c < 4; c++) acc[a][b][c] = 0.f;

    const int a_r  = mw + (lane & 15);
    const int a_cb = (lane >> 4) << 4;
    const int b_r  = nw + (lane & 7) + ((lane >> 4) << 3);
    const int b_cb = (lane & 8) << 1;

    for (int chunk = 0; chunk < 16; chunk++) {
        const int kk = chunk << 6;
#pragma unroll
        for (int j = 0; j < 4; j++) {
            const int t = tid + j * 256;
            const int r = t >> 3, g = t & 7;
            const uint32_t sw = SMEM_SWIZZLE_128B((uint32_t)(r * 128 + g * 16));
            const size_t asrc = (size_t)(m0 + r) * DM + kk + g * 8;
            const size_t bsrc = (size_t)(n0 + r) * DM + kk + g * 8;
            *(uint4*)(smem + sw)         = *(const uint4*)&g_a_hi[asrc];
            *(uint4*)(smem + 16384 + sw) = *(const uint4*)&g_a_lo[asrc];
            *(uint4*)(smem + 32768 + sw) = *(const uint4*)&g_wt_hi[bsrc];
            *(uint4*)(smem + 49152 + sw) = *(const uint4*)&g_wt_lo[bsrc];
        }
        __syncthreads();

#pragma unroll
        for (int ks = 0; ks < 4; ks++) {
            const int cb = ks << 5;
            uint32_t ah[4][4], bb[2][4];
#pragma unroll
            for (int mt = 0; mt < 4; mt++)
                ldsm4(ah[mt], sb + SMEM_SWIZZLE_128B(
                    (uint32_t)((a_r + mt * 16) * 128 + cb + a_cb)));
#pragma unroll
            for (int p = 0; p < 2; p++)
                ldsm4(bb[p], sb + 32768 + SMEM_SWIZZLE_128B(
                    (uint32_t)((b_r + p * 16) * 128 + cb + b_cb)));
#pragma unroll
            for (int mt = 0; mt < 4; mt++)
#pragma unroll
                for (int j = 0; j < 4; j++)
                    mma16816(acc[mt][j], ah[mt], &bb[j >> 1][(j & 1) * 2]);
            {
                uint32_t al[4][4];
#pragma unroll
                for (int mt = 0; mt < 4; mt++)
                    ldsm4(al[mt], sb + 16384 + SMEM_SWIZZLE_128B(
                        (uint32_t)((a_r + mt * 16) * 128 + cb + a_cb)));
#pragma unroll
                for (int mt = 0; mt < 4; mt++)
#pragma unroll
                    for (int j = 0; j < 4; j++)
                        mma16816(acc[mt][j], al[mt], &bb[j >> 1][(j & 1) * 2]);
            }
#pragma unroll
            for (int p = 0; p < 2; p++)
                ldsm4(bb[p], sb + 49152 + SMEM_SWIZZLE_128B(
                    (uint32_t)((b_r + p * 16) * 128 + cb + b_cb)));
#pragma unroll
            for (int mt = 0; mt < 4; mt++)
#pragma unroll
                for (int j = 0; j < 4; j++)
                    mma16816(acc[mt][j], ah[mt], &bb[j >> 1][(j & 1) * 2]);
        }
        __syncthreads();
    }

    const int er = lane >> 2, ec = (lane & 3) << 1;
#pragma unroll
    for (int mt = 0; mt < 4; mt++) {
#pragma unroll
        for (int j = 0; j < 4; j++) {
            const int row = m0 + mw + mt * 16 + er;
            const int col = n0 + nw + j * 8 + ec;
            const float2 bv = *(const float2*)&bias[col];
            float2 lo = make_float2(acc[mt][j][0] + bv.x, acc[mt][j][1] + bv.y);
            float2 hi = make_float2(acc[mt][j][2] + bv.x, acc[mt][j][3] + bv.y);
            *(float2*)&g_qkv[(size_t)row * NCOLS + col] = lo;
            *(float2*)&g_qkv[(size_t)(row + 8) * NCOLS + col] = hi;
        }
    }
}

// ============================================================
// Kernel 2: split qkv into head-major QR = q+r_r, S = q+k+r_w, K, V
// ============================================================
__global__ __launch_bounds__(256)
void split_kernel(const float* __restrict__ rr, const float* __restrict__ rw) {
    const int idx = blockIdx.x * 256 + threadIdx.x;
    const int d = idx & 63;
    const int n = (idx >> 6) & 15;
    const int l = (idx >> 10) & 1023;
    const int b = idx >> 20;
    const int src = (b * LL + l) * NCOLS + n * DHEAD + d;
    const float qv = g_qkv[src];
    const float kv = g_qkv[src + DM];
    const float vv = g_qkv[src + 2 * DM];
    const int dst = ((b * NHEAD + n) * LL + l) * DHEAD + d;
    const float rrv = rr[n * DHEAD + d];
    const float rwv = rw[n * DHEAD + d];
    g_qr[dst] = qv + rrv;
    g_ss[dst] = qv + kv + rwv;
    g_kk[dst] = kv;
    g_vv[dst] = vv;
}

// ============================================================
// Kernel 3 (NEW): attention on mma.sync bf16 splits.
//   score = (QR·K^T + gather(S·P127^T)) / 8
//   T[qi,j] = S[q0+qi]·P127[j],  BDE[qi,ki] = T[qi, 63+ki-qi]
// CTA: 64 q-rows of one (b,n); 16 k-tiles of 64; 8 warps = 4(M)x2(N).
// ============================================================
#define AT_QRH 0
#define AT_QRL 8192
#define AT_SQH 16384
#define AT_SQL 24576
#define AT_KH  32768
#define AT_KL  40960
#define AT_VTH 49152
#define AT_VTL 57344
#define AT_POH 65536
#define AT_POL 81920
#define AT_PBH 98304
#define AT_PBL 106496
#define AT_AC  114688             // fp32, pitch 68
#define AT_T   132096             // fp32, pitch 132
#define AT_MR  165888
#define AT_LR  166144
#define AT_FS  166400
#define AT_SMEM 166656

__global__ __launch_bounds__(256, 1)
void attn_tc_kernel(const float* __restrict__ pos, float* __restrict__ out) {
    extern __shared__ char smem[];
    const uint32_t sb = smem_to_u32(smem);
    float* ACs   = (float*)(smem + AT_AC);
    float* Ts    = (float*)(smem + AT_T);
    float* m_run = (float*)(smem + AT_MR);
    float* l_run = (float*)(smem + AT_LR);
    float* fsc   = (float*)(smem + AT_FS);

    const int tid = threadIdx.x, lane = tid & 31, wid = tid >> 5;
    const int q0 = blockIdx.x << 6;
    const int hn = blockIdx.y, hb = blockIdx.z;
    const int bn = hb * NHEAD + hn;
    const float* qrg = g_qr + (size_t)bn * LL * DHEAD;
    const float* ssg = g_ss + (size_t)bn * LL * DHEAD;
    const float* kg  = g_kk + (size_t)bn * LL * DHEAD;
    const float* vg  = g_vv + (size_t)bn * LL * DHEAD;

    const int mwq = (wid & 3) << 4;     // warp q-row base (0/16/32/48)
    const int ng  = wid >> 2;           // warp col group (0/1)
    const int aRow = lane & 15, aCol = (lane >> 4) << 4;
    const int bRow = (lane & 7) + ((lane >> 4) << 3), bCol = (lane & 8) << 1;
    const int er = lane >> 2, ec = (lane & 3) << 1;

    // prologue: QR & Sq -> bf16 hi/lo (persist all k-tiles)
    for (int i = tid; i < 512; i += 256) {
        const int r = i >> 3, g = i & 7;
        const uint32_t sw = SMEM_SWIZZLE_128B((uint32_t)(r * 128 + g * 16));
        float v[8];
        *(float4*)&v[0] = *(const float4*)&qrg[(q0 + r) * DHEAD + g * 8];
        *(float4*)&v[4] = *(const float4*)&qrg[(q0 + r) * DHEAD + g * 8 + 4];
        uint4 h4, l4; split8(v, h4, l4);
        *(uint4*)(smem + AT_QRH + sw) = h4;
        *(uint4*)(smem + AT_QRL + sw) = l4;
        *(float4*)&v[0] = *(const float4*)&ssg[(q0 + r) * DHEAD + g * 8];
        *(float4*)&v[4] = *(const float4*)&ssg[(q0 + r) * DHEAD + g * 8 + 4];
        split8(v, h4, l4);
        *(uint4*)(smem + AT_SQH + sw) = h4;
        *(uint4*)(smem + AT_SQL + sw) = l4;
    }
    if (tid < 64) { m_run[tid] = -1e30f; l_run[tid] = 0.f; }

    float accO[4][4];
#pragma unroll
    for (int j = 0; j < 4; j++)
#pragma unroll
        for (int c = 0; c < 4; c++) accO[j][c] = 0.f;

    for (int kt = 0; kt < 16; kt++) {
        const int k0 = kt << 6;
        const int pbase = LL + k0 - q0 - 63;    // in [1, 1921]
        __syncthreads();   // previous-iter PV reads done; smem reusable

        // K hi/lo
        for (int i = tid; i < 512; i += 256) {
            const int r = i >> 3, g = i & 7;
            const uint32_t sw = SMEM_SWIZZLE_128B((uint32_t)(r * 128 + g * 16));
            float v[8];
            *(float4*)&v[0] = *(const float4*)&kg[(k0 + r) * DHEAD + g * 8];
            *(float4*)&v[4] = *(const float4*)&kg[(k0 + r) * DHEAD + g * 8 + 4];
            uint4 h4, l4; split8(v, h4, l4);
            *(uint4*)(smem + AT_KH + sw) = h4;
            *(uint4*)(smem + AT_KL + sw) = l4;
        }
        // pos slice (127 rows, pad row 127 with zeros)
        for (int i = tid; i < 1024; i += 256) {
            const int r = i >> 3, g = i & 7;
            const uint32_t sw = SMEM_SWIZZLE_128B((uint32_t)(r * 128 + g * 16));
            float v[8];
            if (r < 127) {
                *(float4*)&v[0] = *(const float4*)&pos[(pbase + r) * DHEAD + g * 8];
                *(float4*)&v[4] = *(const float4*)&pos[(pbase + r) * DHEAD + g * 8 + 4];
            } else {
#pragma unroll
                for (int z = 0; z < 8; z++) v[z] = 0.f;
            }
            uint4 h4, l4; split8(v, h4, l4);
            *(uint4*)(smem + AT_POH + sw) = h4;
            *(uint4*)(smem + AT_POL + sw) = l4;
        }
        // V transposed -> Vt[d][k] hi/lo
        for (int i = tid; i < 4096; i += 256) {
            const int k = i >> 6, d = i & 63;
            const float v = vg[(k0 + k) * DHEAD + d];
            const __nv_bfloat16 h = __float2bfloat16(v);
            const float r = v - __bfloat162float(h);
            const __nv_bfloat16 l = __float2bfloat16(r);
            const uint32_t sw = SMEM_SWIZZLE_128B((uint32_t)(d * 128 + k * 2));
            *(__nv_bfloat16*)(smem + AT_VTH + sw) = h;
            *(__nv_bfloat16*)(smem + AT_VTL + sw) = l;
        }
        __syncthreads();

        // ---- AC = QR · K^T (64x64), 3 chains ----
        {
            float acc[4][4];
#pragma unroll
            for (int j = 0; j < 4; j++)
#pragma unroll
                for (int c = 0; c < 4; c++) acc[j][c] = 0.f;
#pragma unroll
            for (int ks = 0; ks < 4; ks++) {
                const int cb = ks << 5;
                uint32_t ah[4], al[4], bh[2][4];
                ldsm4(ah, sb + AT_QRH + SMEM_SWIZZLE_128B(
                    (uint32_t)((mwq + aRow) * 128 + cb + aCol)));
                ldsm4(al, sb + AT_QRL + SMEM_SWIZZLE_128B(
                    (uint32_t)((mwq + aRow) * 128 + cb + aCol)));
#pragma unroll
                for (int p = 0; p < 2; p++)
                    ldsm4(bh[p], sb + AT_KH + SMEM_SWIZZLE_128B(
                        (uint32_t)((ng * 32 + p * 16 + bRow) * 128 + cb + bCol)));
#pragma unroll
                for (int j = 0; j < 4; j++)
                    mma16816(acc[j], ah, &bh[j >> 1][(j & 1) * 2]);
#pragma unroll
                for (int j = 0; j < 4; j++)
                    mma16816(acc[j], al, &bh[j >> 1][(j & 1) * 2]);
#pragma unroll
                for (int p = 0; p < 2; p++)
                    ldsm4(bh[p], sb + AT_KL + SMEM_SWIZZLE_128B(
                        (uint32_t)((ng * 32 + p * 16 + bRow) * 128 + cb + bCol)));
#pragma unroll
                for (int j = 0; j < 4; j++)
                    mma16816(acc[j], ah, &bh[j >> 1][(j & 1) * 2]);
            }
#pragma unroll
            for (int j = 0; j < 4; j++) {
                const int col = ng * 32 + j * 8 + ec;
                *(float2*)&ACs[(mwq + er) * 68 + col] =
                    make_float2(acc[j][0], acc[j][1]);
                *(float2*)&ACs[(mwq + er + 8) * 68 + col] =
                    make_float2(acc[j][2], acc[j][3]);
            }
        }
        // ---- T = Sq · P127^T (64x128), 3 chains ----
        {
            float accT[8][4];
#pragma unroll
            for (int j = 0; j < 8; j++)
#pragma unroll
                for (int c = 0; c < 4; c++) accT[j][c] = 0.f;
#pragma unroll
            for (int ks = 0; ks < 4; ks++) {
                const int cb = ks << 5;
                uint32_t sh[4], sl[4], pf[4][4];
                ldsm4(sh, sb + AT_SQH + SMEM_SWIZZLE_128B(
                    (uint32_t)((mwq + aRow) * 128 + cb + aCol)));
                ldsm4(sl, sb + AT_SQL + SMEM_SWIZZLE_128B(
                    (uint32_t)((mwq + aRow) * 128 + cb + aCol)));
#pragma unroll
                for (int p = 0; p < 4; p++)
                    ldsm4(pf[p], sb + AT_POH + SMEM_SWIZZLE_128B(
                        (uint32_t)((ng * 64 + p * 16 + bRow) * 128 + cb + bCol)));
#pragma unroll
                for (int j = 0; j < 8; j++)
                    mma16816(accT[j], sh, &pf[j >> 1][(j & 1) * 2]);
#pragma unroll
                for (int j = 0; j < 8; j++)
                    mma16816(accT[j], sl, &pf[j >> 1][(j & 1) * 2]);
#pragma unroll
                for (int p = 0; p < 4; p++)
                    ldsm4(pf[p], sb + AT_POL + SMEM_SWIZZLE_128B(
                        (uint32_t)((ng * 64 + p * 16 + bRow) * 128 + cb + bCol)));
#pragma unroll
                for (int j = 0; j < 8; j++)
                    mma16816(accT[j], sh, &pf[j >> 1][(j & 1) * 2]);
            }
#pragma unroll
            for (int j = 0; j < 8; j++) {
                const int col = ng * 64 + j * 8 + ec;
                *(float2*)&Ts[(mwq + er) * 132 + col] =
                    make_float2(accT[j][0], accT[j][1]);
                *(float2*)&Ts[(mwq + er + 8) * 132 + col] =
                    make_float2(accT[j][2], accT[j][3]);
            }
        }
        __syncthreads();

        // ---- softmax + probs -> bf16 hi/lo ----
        {
            const int row = tid >> 2, sub = tid & 3;
            const int c0 = sub << 4;
            const float* acp = &ACs[row * 68 + c0];
            const float* tp  = &Ts[row * 132 + 63 - row + c0];
            float v[16];
#pragma unroll
            for (int j = 0; j < 16; j++) v[j] = (acp[j] + tp[j]) * 0.125f;
            float mx = v[0];
#pragma unroll
            for (int j = 1; j < 16; j++) mx = fmaxf(mx, v[j]);
            mx = fmaxf(mx, __shfl_xor_sync(0xffffffffu, mx, 1));
            mx = fmaxf(mx, __shfl_xor_sync(0xffffffffu, mx, 2));
            const float mold = m_run[row];
            const float mnew = fmaxf(mold, mx);
            const float fac = __expf(mold - mnew);
            float s = 0.f;
#pragma unroll
            for (int j = 0; j < 16; j++) { v[j] = __expf(v[j] - mnew); s += v[j]; }
            // pack 16 probs -> 2x16B hi + 2x16B lo
            uint4 h0, l0, h1, l1;
            split8(v, h0, l0);
            split8(v + 8, h1, l1);
            const uint32_t sw0 = SMEM_SWIZZLE_128B((uint32_t)(row * 128 + sub * 32));
            const uint32_t sw1 = SMEM_SWIZZLE_128B((uint32_t)(row * 128 + sub * 32 + 16));
            *(uint4*)(smem + AT_PBH + sw0) = h0;
            *(uint4*)(smem + AT_PBH + sw1) = h1;
            *(uint4*)(smem + AT_PBL + sw0) = l0;
            *(uint4*)(smem + AT_PBL + sw1) = l1;
            s += __shfl_xor_sync(0xffffffffu, s, 1);
            s += __shfl_xor_sync(0xffffffffu, s, 2);
            if (sub == 0) {
                l_run[row] = l_run[row] * fac + s;
                m_run[row] = mnew;
                fsc[row] = fac;
            }
        }
        __syncthreads();

        // ---- O rescale + PV (3 chains) ----
        {
            const float f0 = fsc[mwq + er], f1 = fsc[mwq + er + 8];
#pragma unroll
            for (int j = 0; j < 4; j++) {
                accO[j][0] *= f0; accO[j][1] *= f0;
                accO[j][2] *= f1; accO[j][3] *= f1;
            }
#pragma unroll
            for (int ks = 0; ks < 4; ks++) {
                const int cb = ks << 5;
                uint32_t pah[4], pal[4], vf[2][4];
                ldsm4(pah, sb + AT_PBH + SMEM_SWIZZLE_128B(
                    (uint32_t)((mwq + aRow) * 128 + cb + aCol)));
                ldsm4(pal, sb + AT_PBL + SMEM_SWIZZLE_128B(
                    (uint32_t)((mwq + aRow) * 128 + cb + aCol)));
#pragma unroll
                for (int p = 0; p < 2; p++)
                    ldsm4(vf[p], sb + AT_VTH + SMEM_SWIZZLE_128B(
                        (uint32_t)((ng * 32 + p * 16 + bRow) * 128 + cb + bCol)));
#pragma unroll
                for (int j = 0; j < 4; j++)
                    mma16816(accO[j], pah, &vf[j >> 1][(j & 1) * 2]);
#pragma unroll
                for (int j = 0; j < 4; j++)
                    mma16816(accO[j], pal, &vf[j >> 1][(j & 1) * 2]);
#pragma unroll
                for (int p = 0; p < 2; p++)
                    ldsm4(vf[p], sb + AT_VTL + SMEM_SWIZZLE_128B(
                        (uint32_t)((ng * 32 + p * 16 + bRow) * 128 + cb + bCol)));
#pragma unroll
                for (int j = 0; j < 4; j++)
                    mma16816(accO[j], pah, &vf[j >> 1][(j & 1) * 2]);
            }
        }
    }

    // finalize: out[hb, q, hn*64 + d] = O / l
    {
        const float inv0 = 1.0f / l_run[mwq + er];
        const float inv1 = 1.0f / l_run[mwq + er + 8];
        const int r0 = q0 + mwq + er;
#pragma unroll
        for (int j = 0; j < 4; j++) {
            const int col = hn * 64 + ng * 32 + j * 8 + ec;
            *(float2*)&out[(size_t)(hb * LL + r0) * DM + col] =
                make_float2(accO[j][0] * inv0, accO[j][1] * inv0);
            *(float2*)&out[(size_t)(hb * LL + r0 + 8) * DM + col] =
                make_float2(accO[j][2] * inv1, accO[j][3] * inv1);
        }
    }
}

// ============================================================
extern "C" void kernel_launch(void* const* d_in, const int* in_sizes, int n_in,
                              void* d_out, int out_size) {
    const float* x   = (const float*)d_in[0];
    const float* pos = (const float*)d_in[1];
    const float* W   = (const float*)d_in[2];
    const float* bqk = (const float*)d_in[3];
    const float* rr  = (const float*)d_in[4];
    const float* rw  = (const float*)d_in[5];
    float* out = (float*)d_out;

    cudaFuncSetAttribute(qkv_tc_kernel,
                         cudaFuncAttributeMaxDynamicSharedMemorySize, QK_SMEM_TOTAL);
    cudaFuncSetAttribute(attn_tc_kernel,
                         cudaFuncAttributeMaxDynamicSharedMemorySize, AT_SMEM);

    conv_x_kernel<<<(MROWS * DM) / 256, 256>>>(x);
    conv_w_kernel<<<dim3(NCOLS / 32, DM / 32), dim3(32, 8)>>>(W);
    qkv_tc_kernel<<<dim3(NCOLS / 128, MROWS / 128), 256, QK_SMEM_TOTAL>>>(bqk);
    split_kernel<<<(BB * LL * NHEAD * DHEAD) / 256, 256>>>(rr, rw);
    attn_tc_kernel<<<dim3(LL / 64, NHEAD, BB), 256, AT_SMEM>>>(pos, out);
}

// round 13
// speedup vs baseline: 3.1552x; 1.6408x over previous
#include <cuda_runtime.h>
#include <cuda_bf16.h>
#include <cstdint>

#define BB 4
#define LL 1024
#define DM 1024
#define NHEAD 16
#define DHEAD 64
#define MROWS (BB * LL)      // 4096
#define NCOLS (3 * DM)       // 3072
#define NBH (BB * NHEAD * LL * DHEAD)   // 4M elements

// ---- scratch (static device globals; no runtime allocation) ----
__device__ float g_qkv[MROWS * NCOLS];          // 48 MB
__device__ float g_vv[NBH];                     // 16 MB (fp32 V, head-major, for vt staging)
// bf16 hi/lo operands for attention
__device__ __nv_bfloat16 g_qrh[NBH], g_qrl[NBH];
__device__ __nv_bfloat16 g_ssh[NBH], g_ssl[NBH];
__device__ __nv_bfloat16 g_kh[NBH],  g_kl[NBH];
__device__ __nv_bfloat16 g_vth[NBH], g_vtl[NBH];     // [bn][d][L]
__device__ __nv_bfloat16 g_posh[2 * LL * DHEAD], g_posl[2 * LL * DHEAD];
// bf16 split operands for mma.sync qkv GEMM
__device__ __nv_bfloat16 g_a_hi[MROWS * DM];
__device__ __nv_bfloat16 g_a_lo[MROWS * DM];
__device__ __nv_bfloat16 g_wt_hi[NCOLS * DM];
__device__ __nv_bfloat16 g_wt_lo[NCOLS * DM];

// ============================================================
// helpers
// ============================================================
__device__ __forceinline__ uint32_t smem_to_u32(const void* p) {
    uint32_t a;
    asm("{ .reg .u64 t; cvta.to.shared.u64 t, %1; cvt.u32.u64 %0, t; }"
        : "=r"(a) : "l"(p));
    return a;
}
#define SMEM_SWIZZLE_128B(byte_offset) \
    ((byte_offset) ^ (((byte_offset) >> 3) & 0x70))

__device__ __forceinline__ void ldsm4(uint32_t* r, uint32_t addr) {
    asm volatile("ldmatrix.sync.aligned.m8n8.x4.shared.b16 {%0,%1,%2,%3}, [%4];"
        : "=r"(r[0]), "=r"(r[1]), "=r"(r[2]), "=r"(r[3]) : "r"(addr));
}
__device__ __forceinline__ void mma16816(float* c, const uint32_t* a, const uint32_t* b) {
    asm volatile(
        "mma.sync.aligned.m16n8k16.row.col.f32.bf16.bf16.f32 "
        "{%0,%1,%2,%3}, {%4,%5,%6,%7}, {%8,%9}, {%0,%1,%2,%3};"
        : "+f"(c[0]), "+f"(c[1]), "+f"(c[2]), "+f"(c[3])
        : "r"(a[0]), "r"(a[1]), "r"(a[2]), "r"(a[3]), "r"(b[0]), "r"(b[1]));
}
__device__ __forceinline__ void cpa16(uint32_t dst, const void* src) {
    asm volatile("cp.async.cg.shared.global [%0], [%1], 16;"
        :: "r"(dst), "l"(src) : "memory");
}
#define CP_COMMIT() asm volatile("cp.async.commit_group;" ::: "memory")
#define CP_WAIT1()  asm volatile("cp.async.wait_group 1;" ::: "memory")

// split 8 fp32 into 8 bf16 hi + 8 bf16 lo, packed as uint4 each
__device__ __forceinline__ void split8(const float* v, uint4& h4, uint4& l4) {
    uint32_t h[4], l[4];
#pragma unroll
    for (int i = 0; i < 4; i++) {
        float x = v[2 * i], y = v[2 * i + 1];
        __nv_bfloat16 hx = __float2bfloat16(x), hy = __float2bfloat16(y);
        float rx = x - __bfloat162float(hx), ry = y - __bfloat162float(hy);
        __nv_bfloat16 lx = __float2bfloat16(rx), ly = __float2bfloat16(ry);
        h[i] = (uint32_t)(*(uint16_t*)&hx) | ((uint32_t)(*(uint16_t*)&hy) << 16);
        l[i] = (uint32_t)(*(uint16_t*)&lx) | ((uint32_t)(*(uint16_t*)&ly) << 16);
    }
    h4 = make_uint4(h[0], h[1], h[2], h[3]);
    l4 = make_uint4(l[0], l[1], l[2], l[3]);
}
__device__ __forceinline__ void split1(float v, __nv_bfloat16& h, __nv_bfloat16& l) {
    h = __float2bfloat16(v);
    l = __float2bfloat16(v - __bfloat162float(h));
}

// ============================================================
// Conversion kernels
// ============================================================
__global__ __launch_bounds__(256)
void conv_x_kernel(const float* __restrict__ x) {
    const int i = blockIdx.x * 256 + threadIdx.x;
    __nv_bfloat16 h, l; split1(x[i], h, l);
    g_a_hi[i] = h; g_a_lo[i] = l;
}

__global__ __launch_bounds__(256)
void conv_w_kernel(const float* __restrict__ W) {
    __shared__ float t[32][33];
    const int tx = threadIdx.x, ty = threadIdx.y;
    const int n0 = blockIdx.x * 32, k0 = blockIdx.y * 32;
#pragma unroll
    for (int i = 0; i < 4; i++)
        t[ty + i * 8][tx] = W[(k0 + ty + i * 8) * NCOLS + n0 + tx];
    __syncthreads();
#pragma unroll
    for (int i = 0; i < 4; i++) {
        const int n = n0 + ty + i * 8;
        const int k = k0 + tx;
        __nv_bfloat16 h, l; split1(t[tx][ty + i * 8], h, l);
        g_wt_hi[n * DM + k] = h; g_wt_lo[n * DM + k] = l;
    }
}

__global__ __launch_bounds__(256)
void pos_split_kernel(const float* __restrict__ pos) {
    const int i = blockIdx.x * 256 + threadIdx.x;   // < 2048*64
    __nv_bfloat16 h, l; split1(pos[i], h, l);
    g_posh[i] = h; g_posl[i] = l;
}

// ============================================================
// Kernel 1: qkv = x @ W_qkv + b_qkv via mma.sync bf16 2-term split
// ============================================================
#define QK_SMEM_TOTAL 65536

__global__ __launch_bounds__(256, 2)
void qkv_tc_kernel(const float* __restrict__ bias) {
    extern __shared__ char smem[];
    const uint32_t sb = smem_to_u32(smem);
    const int tid = threadIdx.x;
    const int lane = tid & 31, wid = tid >> 5;
    const int n0 = blockIdx.x << 7, m0 = blockIdx.y << 7;
    const int mw = (wid & 1) << 6;
    const int nw = (wid >> 1) << 5;

    float acc[4][4][4];
#pragma unroll
    for (int a = 0; a < 4; a++)
#pragma unroll
        for (int b = 0; b < 4; b++)
#pragma unroll
            for (int c = 0; c < 4; c++) acc[a][b][c] = 0.f;

    const int a_r  = mw + (lane & 15);
    const int a_cb = (lane >> 4) << 4;
    const int b_r  = nw + (lane & 7) + ((lane >> 4) << 3);
    const int b_cb = (lane & 8) << 1;

    for (int chunk = 0; chunk < 16; chunk++) {
        const int kk = chunk << 6;
#pragma unroll
        for (int j = 0; j < 4; j++) {
            const int t = tid + j * 256;
            const int r = t >> 3, g = t & 7;
            const uint32_t sw = SMEM_SWIZZLE_128B((uint32_t)(r * 128 + g * 16));
            const size_t asrc = (size_t)(m0 + r) * DM + kk + g * 8;
            const size_t bsrc = (size_t)(n0 + r) * DM + kk + g * 8;
            *(uint4*)(smem + sw)         = *(const uint4*)&g_a_hi[asrc];
            *(uint4*)(smem + 16384 + sw) = *(const uint4*)&g_a_lo[asrc];
            *(uint4*)(smem + 32768 + sw) = *(const uint4*)&g_wt_hi[bsrc];
            *(uint4*)(smem + 49152 + sw) = *(const uint4*)&g_wt_lo[bsrc];
        }
        __syncthreads();

#pragma unroll
        for (int ks = 0; ks < 4; ks++) {
            const int cb = ks << 5;
            uint32_t ah[4][4], bb[2][4];
#pragma unroll
            for (int mt = 0; mt < 4; mt++)
                ldsm4(ah[mt], sb + SMEM_SWIZZLE_128B(
                    (uint32_t)((a_r + mt * 16) * 128 + cb + a_cb)));
#pragma unroll
            for (int p = 0; p < 2; p++)
                ldsm4(bb[p], sb + 32768 + SMEM_SWIZZLE_128B(
                    (uint32_t)((b_r + p * 16) * 128 + cb + b_cb)));
#pragma unroll
            for (int mt = 0; mt < 4; mt++)
#pragma unroll
                for (int j = 0; j < 4; j++)
                    mma16816(acc[mt][j], ah[mt], &bb[j >> 1][(j & 1) * 2]);
            {
                uint32_t al[4][4];
#pragma unroll
                for (int mt = 0; mt < 4; mt++)
                    ldsm4(al[mt], sb + 16384 + SMEM_SWIZZLE_128B(
                        (uint32_t)((a_r + mt * 16) * 128 + cb + a_cb)));
#pragma unroll
                for (int mt = 0; mt < 4; mt++)
#pragma unroll
                    for (int j = 0; j < 4; j++)
                        mma16816(acc[mt][j], al[mt], &bb[j >> 1][(j & 1) * 2]);
            }
#pragma unroll
            for (int p = 0; p < 2; p++)
                ldsm4(bb[p], sb + 49152 + SMEM_SWIZZLE_128B(
                    (uint32_t)((b_r + p * 16) * 128 + cb + b_cb)));
#pragma unroll
            for (int mt = 0; mt < 4; mt++)
#pragma unroll
                for (int j = 0; j < 4; j++)
                    mma16816(acc[mt][j], ah[mt], &bb[j >> 1][(j & 1) * 2]);
        }
        __syncthreads();
    }

    const int er = lane >> 2, ec = (lane & 3) << 1;
#pragma unroll
    for (int mt = 0; mt < 4; mt++) {
#pragma unroll
        for (int j = 0; j < 4; j++) {
            const int row = m0 + mw + mt * 16 + er;
            const int col = n0 + nw + j * 8 + ec;
            const float2 bv = *(const float2*)&bias[col];
            float2 lo = make_float2(acc[mt][j][0] + bv.x, acc[mt][j][1] + bv.y);
            float2 hi = make_float2(acc[mt][j][2] + bv.x, acc[mt][j][3] + bv.y);
            *(float2*)&g_qkv[(size_t)row * NCOLS + col] = lo;
            *(float2*)&g_qkv[(size_t)(row + 8) * NCOLS + col] = hi;
        }
    }
}

// ============================================================
// Kernel 2: split qkv -> bf16 hi/lo head-major QR, S, K; fp32 V
// ============================================================
__global__ __launch_bounds__(256)
void split_kernel(const float* __restrict__ rr, const float* __restrict__ rw) {
    const int idx = blockIdx.x * 256 + threadIdx.x;
    const int d = idx & 63;
    const int n = (idx >> 6) & 15;
    const int l = (idx >> 10) & 1023;
    const int b = idx >> 20;
    const int src = (b * LL + l) * NCOLS + n * DHEAD + d;
    const float qv = g_qkv[src];
    const float kv = g_qkv[src + DM];
    const float vv = g_qkv[src + 2 * DM];
    const int dst = ((b * NHEAD + n) * LL + l) * DHEAD + d;
    const float qr = qv + rr[n * DHEAD + d];
    const float ss = qv + kv + rw[n * DHEAD + d];
    __nv_bfloat16 h, l2;
    split1(qr, h, l2); g_qrh[dst] = h; g_qrl[dst] = l2;
    split1(ss, h, l2); g_ssh[dst] = h; g_ssl[dst] = l2;
    split1(kv, h, l2); g_kh[dst] = h;  g_kl[dst] = l2;
    g_vv[dst] = vv;
}

// ============================================================
// Kernel 2b: V transpose per head -> Vt[bn][d][L] bf16 hi/lo
// ============================================================
__global__ __launch_bounds__(256)
void vt_kernel() {
    __shared__ float s[64][65];
    const int tid = threadIdx.x;
    const int l0 = blockIdx.x << 6;
    const int bn = blockIdx.y;
#pragma unroll
    for (int i = 0; i < 16; i++) {
        const int idx = tid + i * 256;
        const int l = idx >> 6, d = idx & 63;
        s[l][d] = g_vv[((size_t)bn * LL + l0 + l) * DHEAD + d];
    }
    __syncthreads();
#pragma unroll
    for (int i = 0; i < 16; i++) {
        const int idx = tid + i * 256;
        const int d = idx >> 6, l = idx & 63;
        __nv_bfloat16 h, lo; split1(s[l][d], h, lo);
        const size_t o = ((size_t)bn * DHEAD + d) * LL + l0 + l;
        g_vth[o] = h; g_vtl[o] = lo;
    }
}

// ============================================================
// Kernel 3: attention, mma.sync + cp.async double-buffered pipeline
// ============================================================
#define AT_QRH 0
#define AT_QRL 8192
#define AT_SQH 16384
#define AT_SQL 24576
#define AT_PBH 32768
#define AT_PBL 40960
#define AT_T   49152            // fp32, 64 rows x pitch 132 = 33792 B
#define AT_MR  82944
#define AT_LR  83200
#define AT_FS  83456
#define AT_BUF0 83968           // per-buffer: KH|KL|VTH|VTL|POH|POL
#define AT_BUFSZ 65536
#define AT_SMEM (AT_BUF0 + 2 * AT_BUFSZ)   // 215040

__device__ __forceinline__ void at_prefetch(
    uint32_t sbuf, int tid,
    const __nv_bfloat16* kh, const __nv_bfloat16* kl,
    const __nv_bfloat16* vth, const __nv_bfloat16* vtl,
    int k0t, int pb)
{
#pragma unroll
    for (int c = 0; c < 2; c++) {
        const int idx = tid + c * 256;
        const int r = idx >> 3, g = idx & 7;
        const uint32_t sw = SMEM_SWIZZLE_128B((uint32_t)(r * 128 + g * 16));
        cpa16(sbuf + sw,         kh  + (k0t + r) * DHEAD + g * 8);
        cpa16(sbuf + 8192 + sw,  kl  + (k0t + r) * DHEAD + g * 8);
        cpa16(sbuf + 16384 + sw, vth + (size_t)r * LL + k0t + g * 8);
        cpa16(sbuf + 24576 + sw, vtl + (size_t)r * LL + k0t + g * 8);
    }
#pragma unroll
    for (int c = 0; c < 4; c++) {
        const int idx = tid + c * 256;
        const int r = idx >> 3, g = idx & 7;
        int row = pb + r; if (row > 2 * LL - 1) row = 2 * LL - 1;
        const uint32_t sw = SMEM_SWIZZLE_128B((uint32_t)(r * 128 + g * 16));
        cpa16(sbuf + 32768 + sw, g_posh + row * DHEAD + g * 8);
        cpa16(sbuf + 49152 + sw, g_posl + row * DHEAD + g * 8);
    }
}

__global__ __launch_bounds__(256, 1)
void attn_tc_kernel(float* __restrict__ out) {
    extern __shared__ char smem[];
    const uint32_t sb = smem_to_u32(smem);
    float* Ts    = (float*)(smem + AT_T);
    float* m_run = (float*)(smem + AT_MR);
    float* l_run = (float*)(smem + AT_LR);
    float* fsc   = (float*)(smem + AT_FS);

    const int tid = threadIdx.x, lane = tid & 31, wid = tid >> 5;
    const int q0 = blockIdx.x << 6;
    const int hn = blockIdx.y, hb = blockIdx.z;
    const int bn = hb * NHEAD + hn;
    const size_t hoff = (size_t)bn * LL * DHEAD;
    const __nv_bfloat16* qrh = g_qrh + hoff;
    const __nv_bfloat16* qrl = g_qrl + hoff;
    const __nv_bfloat16* ssh = g_ssh + hoff;
    const __nv_bfloat16* ssl = g_ssl + hoff;
    const __nv_bfloat16* kh  = g_kh + hoff;
    const __nv_bfloat16* kl  = g_kl + hoff;
    const __nv_bfloat16* vth = g_vth + hoff;   // [d][L]
    const __nv_bfloat16* vtl = g_vtl + hoff;

    const int mwq = (wid & 3) << 4;
    const int ng  = wid >> 2;
    const int aRow = lane & 15, aCol = (lane >> 4) << 4;
    const int bRow = (lane & 7) + ((lane >> 4) << 3), bCol = (lane & 8) << 1;
    const int er = lane >> 2, ec = (lane & 3) << 1;

    // prologue: QR/S copies + tile0 prefetch -> group 1
#pragma unroll
    for (int c = 0; c < 2; c++) {
        const int idx = tid + c * 256;
        const int r = idx >> 3, g = idx & 7;
        const uint32_t sw = SMEM_SWIZZLE_128B((uint32_t)(r * 128 + g * 16));
        const int so = (q0 + r) * DHEAD + g * 8;
        cpa16(sb + AT_QRH + sw, qrh + so);
        cpa16(sb + AT_QRL + sw, qrl + so);
        cpa16(sb + AT_SQH + sw, ssh + so);
        cpa16(sb + AT_SQL + sw, ssl + so);
    }
    at_prefetch(sb + AT_BUF0, tid, kh, kl, vth, vtl, 0, LL - q0 - 63);
    CP_COMMIT();

    if (tid < 64) { m_run[tid] = -1e30f; l_run[tid] = 0.f; }

    float accO[4][4];
#pragma unroll
    for (int j = 0; j < 4; j++)
#pragma unroll
        for (int c = 0; c < 4; c++) accO[j][c] = 0.f;

    for (int kt = 0; kt < 16; kt++) {
        __syncthreads();    // all warps done reading buf (kt+1)&1 from iter kt-1
        const int kn = (kt < 15) ? kt + 1 : 15;
        at_prefetch(sb + AT_BUF0 + ((kt + 1) & 1) * AT_BUFSZ, tid,
                    kh, kl, vth, vtl, kn << 6, LL + (kn << 6) - q0 - 63);
        CP_COMMIT();
        CP_WAIT1();         // tile kt data resident
        __syncthreads();

        const uint32_t bufb = sb + AT_BUF0 + (kt & 1) * AT_BUFSZ;

        // ---- AC = QR · K^T (64x64) into regs; T = Sq · P127^T (64x128) -> Ts ----
        float acc[4][4];
#pragma unroll
        for (int j = 0; j < 4; j++)
#pragma unroll
            for (int c = 0; c < 4; c++) acc[j][c] = 0.f;
#pragma unroll
        for (int ks = 0; ks < 4; ks++) {
            const int cb = ks << 5;
            uint32_t ah[4], al[4], bh[2][4];
            ldsm4(ah, sb + AT_QRH + SMEM_SWIZZLE_128B(
                (uint32_t)((mwq + aRow) * 128 + cb + aCol)));
            ldsm4(al, sb + AT_QRL + SMEM_SWIZZLE_128B(
                (uint32_t)((mwq + aRow) * 128 + cb + aCol)));
#pragma unroll
            for (int p = 0; p < 2; p++)
                ldsm4(bh[p], bufb + SMEM_SWIZZLE_128B(
                    (uint32_t)((ng * 32 + p * 16 + bRow) * 128 + cb + bCol)));
#pragma unroll
            for (int j = 0; j < 4; j++)
                mma16816(acc[j], ah, &bh[j >> 1][(j & 1) * 2]);
#pragma unroll
            for (int j = 0; j < 4; j++)
                mma16816(acc[j], al, &bh[j >> 1][(j & 1) * 2]);
#pragma unroll
            for (int p = 0; p < 2; p++)
                ldsm4(bh[p], bufb + 8192 + SMEM_SWIZZLE_128B(
                    (uint32_t)((ng * 32 + p * 16 + bRow) * 128 + cb + bCol)));
#pragma unroll
            for (int j = 0; j < 4; j++)
                mma16816(acc[j], ah, &bh[j >> 1][(j & 1) * 2]);
        }
        {
            float accT[8][4];
#pragma unroll
            for (int j = 0; j < 8; j++)
#pragma unroll
                for (int c = 0; c < 4; c++) accT[j][c] = 0.f;
#pragma unroll
            for (int ks = 0; ks < 4; ks++) {
                const int cb = ks << 5;
                uint32_t sh[4], sl[4], pf[4][4];
                ldsm4(sh, sb + AT_SQH + SMEM_SWIZZLE_128B(
                    (uint32_t)((mwq + aRow) * 128 + cb + aCol)));
                ldsm4(sl, sb + AT_SQL + SMEM_SWIZZLE_128B(
                    (uint32_t)((mwq + aRow) * 128 + cb + aCol)));
#pragma unroll
                for (int p = 0; p < 4; p++)
                    ldsm4(pf[p], bufb + 32768 + SMEM_SWIZZLE_128B(
                        (uint32_t)((ng * 64 + p * 16 + bRow) * 128 + cb + bCol)));
#pragma unroll
                for (int j = 0; j < 8; j++)
                    mma16816(accT[j], sh, &pf[j >> 1][(j & 1) * 2]);
#pragma unroll
                for (int j = 0; j < 8; j++)
                    mma16816(accT[j], sl, &pf[j >> 1][(j & 1) * 2]);
#pragma unroll
                for (int p = 0; p < 4; p++)
                    ldsm4(pf[p], bufb + 49152 + SMEM_SWIZZLE_128B(
                        (uint32_t)((ng * 64 + p * 16 + bRow) * 128 + cb + bCol)));
#pragma unroll
                for (int j = 0; j < 8; j++)
                    mma16816(accT[j], sh, &pf[j >> 1][(j & 1) * 2]);
            }
#pragma unroll
            for (int j = 0; j < 8; j++) {
                const int col = ng * 64 + j * 8 + ec;
                *(float2*)&Ts[(mwq + er) * 132 + col] =
                    make_float2(accT[j][0], accT[j][1]);
                *(float2*)&Ts[(mwq + er + 8) * 132 + col] =
                    make_float2(accT[j][2], accT[j][3]);
            }
        }
        __syncthreads();

        // ---- fold AC into Ts at gathered positions ----
#pragma unroll
        for (int j = 0; j < 4; j++) {
            const int ki = ng * 32 + j * 8 + ec;
            const int r0 = mwq + er, r1 = r0 + 8;
            Ts[r0 * 132 + 63 - r0 + ki]     += acc[j][0];
            Ts[r0 * 132 + 63 - r0 + ki + 1] += acc[j][1];
            Ts[r1 * 132 + 63 - r1 + ki]     += acc[j][2];
            Ts[r1 * 132 + 63 - r1 + ki + 1] += acc[j][3];
        }
        __syncthreads();

        // ---- softmax + probs -> bf16 hi/lo ----
        {
            const int row = tid >> 2, sub = tid & 3;
            const int c0 = sub << 4;
            const float* tp = &Ts[row * 132 + 63 - row + c0];
            float v[16];
#pragma unroll
            for (int j = 0; j < 16; j++) v[j] = tp[j] * 0.125f;
            float mx = v[0];
#pragma unroll
            for (int j = 1; j < 16; j++) mx = fmaxf(mx, v[j]);
            mx = fmaxf(mx, __shfl_xor_sync(0xffffffffu, mx, 1));
            mx = fmaxf(mx, __shfl_xor_sync(0xffffffffu, mx, 2));
            const float mold = m_run[row];
            const float mnew = fmaxf(mold, mx);
            const float fac = __expf(mold - mnew);
            float s = 0.f;
#pragma unroll
            for (int j = 0; j < 16; j++) { v[j] = __expf(v[j] - mnew); s += v[j]; }
            uint4 h0, l0, h1, l1;
            split8(v, h0, l0);
            split8(v + 8, h1, l1);
            const uint32_t sw0 = SMEM_SWIZZLE_128B((uint32_t)(row * 128 + sub * 32));
            const uint32_t sw1 = SMEM_SWIZZLE_128B((uint32_t)(row * 128 + sub * 32 + 16));
            *(uint4*)(smem + AT_PBH + sw0) = h0;
            *(uint4*)(smem + AT_PBH + sw1) = h1;
            *(uint4*)(smem + AT_PBL + sw0) = l0;
            *(uint4*)(smem + AT_PBL + sw1) = l1;
            s += __shfl_xor_sync(0xffffffffu, s, 1);
            s += __shfl_xor_sync(0xffffffffu, s, 2);
            if (sub == 0) {
                l_run[row] = l_run[row] * fac + s;
                m_run[row] = mnew;
                fsc[row] = fac;
            }
        }
        __syncthreads();

        // ---- O rescale + PV (3 chains) ----
        {
            const float f0 = fsc[mwq + er], f1 = fsc[mwq + er + 8];
#pragma unroll
            for (int j = 0; j < 4; j++) {
                accO[j][0] *= f0; accO[j][1] *= f0;
                accO[j][2] *= f1; accO[j][3] *= f1;
            }
#pragma unroll
            for (int ks = 0; ks < 4; ks++) {
                const int cb = ks << 5;
                uint32_t pah[4], pal[4], vf[2][4];
                ldsm4(pah, sb + AT_PBH + SMEM_SWIZZLE_128B(
                    (uint32_t)((mwq + aRow) * 128 + cb + aCol)));
                ldsm4(pal, sb + AT_PBL + SMEM_SWIZZLE_128B(
                    (uint32_t)((mwq + aRow) * 128 + cb + aCol)));
#pragma unroll
                for (int p = 0; p < 2; p++)
                    ldsm4(vf[p], bufb + 16384 + SMEM_SWIZZLE_128B(
                        (uint32_t)((ng * 32 + p * 16 + bRow) * 128 + cb + bCol)));
#pragma unroll
                for (int j = 0; j < 4; j++)
                    mma16816(accO[j], pah, &vf[j >> 1][(j & 1) * 2]);
#pragma unroll
                for (int j = 0; j < 4; j++)
                    mma16816(accO[j], pal, &vf[j >> 1][(j & 1) * 2]);
#pragma unroll
                for (int p = 0; p < 2; p++)
                    ldsm4(vf[p], bufb + 24576 + SMEM_SWIZZLE_128B(
                        (uint32_t)((ng * 32 + p * 16 + bRow) * 128 + cb + bCol)));
#pragma unroll
                for (int j = 0; j < 4; j++)
                    mma16816(accO[j], pah, &vf[j >> 1][(j & 1) * 2]);
            }
        }
    }

    // finalize: out[hb, q, hn*64 + d] = O / l
    {
        const float inv0 = 1.0f / l_run[mwq + er];
        const float inv1 = 1.0f / l_run[mwq + er + 8];
        const int r0 = q0 + mwq + er;
#pragma unroll
        for (int j = 0; j < 4; j++) {
            const int col = hn * 64 + ng * 32 + j * 8 + ec;
            *(float2*)&out[(size_t)(hb * LL + r0) * DM + col] =
                make_float2(accO[j][0] * inv0, accO[j][1] * inv0);
            *(float2*)&out[(size_t)(hb * LL + r0 + 8) * DM + col] =
                make_float2(accO[j][2] * inv1, accO[j][3] * inv1);
        }
    }
}

// ============================================================
extern "C" void kernel_launch(void* const* d_in, const int* in_sizes, int n_in,
                              void* d_out, int out_size) {
    const float* x   = (const float*)d_in[0];
    const float* pos = (const float*)d_in[1];
    const float* W   = (const float*)d_in[2];
    const float* bqk = (const float*)d_in[3];
    const float* rr  = (const float*)d_in[4];
    const float* rw  = (const float*)d_in[5];
    float* out = (float*)d_out;

    cudaFuncSetAttribute(qkv_tc_kernel,
                         cudaFuncAttributeMaxDynamicSharedMemorySize, QK_SMEM_TOTAL);
    cudaFuncSetAttribute(attn_tc_kernel,
                         cudaFuncAttributeMaxDynamicSharedMemorySize, AT_SMEM);

    conv_x_kernel<<<(MROWS * DM) / 256, 256>>>(x);
    conv_w_kernel<<<dim3(NCOLS / 32, DM / 32), dim3(32, 8)>>>(W);
    pos_split_kernel<<<(2 * LL * DHEAD) / 256, 256>>>(pos);
    qkv_tc_kernel<<<dim3(NCOLS / 128, MROWS / 128), 256, QK_SMEM_TOTAL>>>(bqk);
    split_kernel<<<(BB * LL * NHEAD * DHEAD) / 256, 256>>>(rr, rw);
    vt_kernel<<<dim3(LL / 64, BB * NHEAD), 256>>>();
    attn_tc_kernel<<<dim3(LL / 64, NHEAD, BB), 256, AT_SMEM>>>(out);
}

// round 14
// speedup vs baseline: 3.2516x; 1.0306x over previous
#include <cuda_runtime.h>
#include <cuda_bf16.h>
#include <cstdint>

#define BB 4
#define LL 1024
#define DM 1024
#define NHEAD 16
#define DHEAD 64
#define MROWS (BB * LL)      // 4096
#define NCOLS (3 * DM)       // 3072
#define NBH (BB * NHEAD * LL * DHEAD)   // 4M elements

// ---- scratch (static device globals; no runtime allocation) ----
__device__ float g_qkv[MROWS * NCOLS];          // 48 MB
// bf16 hi/lo operands for attention
__device__ __nv_bfloat16 g_qrh[NBH], g_qrl[NBH];
__device__ __nv_bfloat16 g_ssh[NBH], g_ssl[NBH];
__device__ __nv_bfloat16 g_kh[NBH],  g_kl[NBH];
__device__ __nv_bfloat16 g_vth[NBH], g_vtl[NBH];     // [bn][d][L]
__device__ __nv_bfloat16 g_posh[2 * LL * DHEAD], g_posl[2 * LL * DHEAD];
// bf16 split operands for mma.sync qkv GEMM
__device__ __nv_bfloat16 g_a_hi[MROWS * DM];
__device__ __nv_bfloat16 g_a_lo[MROWS * DM];
__device__ __nv_bfloat16 g_wt_hi[NCOLS * DM];
__device__ __nv_bfloat16 g_wt_lo[NCOLS * DM];

// ============================================================
// helpers
// ============================================================
__device__ __forceinline__ uint32_t smem_to_u32(const void* p) {
    uint32_t a;
    asm("{ .reg .u64 t; cvta.to.shared.u64 t, %1; cvt.u32.u64 %0, t; }"
        : "=r"(a) : "l"(p));
    return a;
}
#define SMEM_SWIZZLE_128B(byte_offset) \
    ((byte_offset) ^ (((byte_offset) >> 3) & 0x70))

__device__ __forceinline__ void ldsm4(uint32_t* r, uint32_t addr) {
    asm volatile("ldmatrix.sync.aligned.m8n8.x4.shared.b16 {%0,%1,%2,%3}, [%4];"
        : "=r"(r[0]), "=r"(r[1]), "=r"(r[2]), "=r"(r[3]) : "r"(addr));
}
__device__ __forceinline__ void mma16816(float* c, const uint32_t* a, const uint32_t* b) {
    asm volatile(
        "mma.sync.aligned.m16n8k16.row.col.f32.bf16.bf16.f32 "
        "{%0,%1,%2,%3}, {%4,%5,%6,%7}, {%8,%9}, {%0,%1,%2,%3};"
        : "+f"(c[0]), "+f"(c[1]), "+f"(c[2]), "+f"(c[3])
        : "r"(a[0]), "r"(a[1]), "r"(a[2]), "r"(a[3]), "r"(b[0]), "r"(b[1]));
}
__device__ __forceinline__ void cpa16(uint32_t dst, const void* src) {
    asm volatile("cp.async.cg.shared.global [%0], [%1], 16;"
        :: "r"(dst), "l"(src) : "memory");
}
#define CP_COMMIT() asm volatile("cp.async.commit_group;" ::: "memory")
#define CP_WAIT1()  asm volatile("cp.async.wait_group 1;" ::: "memory")

// split 8 fp32 into 8 bf16 hi + 8 bf16 lo, packed as uint4 each
__device__ __forceinline__ void split8(const float* v, uint4& h4, uint4& l4) {
    uint32_t h[4], l[4];
#pragma unroll
    for (int i = 0; i < 4; i++) {
        float x = v[2 * i], y = v[2 * i + 1];
        __nv_bfloat16 hx = __float2bfloat16(x), hy = __float2bfloat16(y);
        float rx = x - __bfloat162float(hx), ry = y - __bfloat162float(hy);
        __nv_bfloat16 lx = __float2bfloat16(rx), ly = __float2bfloat16(ry);
        h[i] = (uint32_t)(*(uint16_t*)&hx) | ((uint32_t)(*(uint16_t*)&hy) << 16);
        l[i] = (uint32_t)(*(uint16_t*)&lx) | ((uint32_t)(*(uint16_t*)&ly) << 16);
    }
    h4 = make_uint4(h[0], h[1], h[2], h[3]);
    l4 = make_uint4(l[0], l[1], l[2], l[3]);
}
__device__ __forceinline__ void split1(float v, __nv_bfloat16& h, __nv_bfloat16& l) {
    h = __float2bfloat16(v);
    l = __float2bfloat16(v - __bfloat162float(h));
}

// ============================================================
// Conversion kernels
// ============================================================
__global__ __launch_bounds__(256)
void conv_x_kernel(const float* __restrict__ x) {
    const int i = blockIdx.x * 256 + threadIdx.x;
    __nv_bfloat16 h, l; split1(x[i], h, l);
    g_a_hi[i] = h; g_a_lo[i] = l;
}

__global__ __launch_bounds__(256)
void conv_w_kernel(const float* __restrict__ W) {
    __shared__ float t[32][33];
    const int tx = threadIdx.x, ty = threadIdx.y;
    const int n0 = blockIdx.x * 32, k0 = blockIdx.y * 32;
#pragma unroll
    for (int i = 0; i < 4; i++)
        t[ty + i * 8][tx] = W[(k0 + ty + i * 8) * NCOLS + n0 + tx];
    __syncthreads();
#pragma unroll
    for (int i = 0; i < 4; i++) {
        const int n = n0 + ty + i * 8;
        const int k = k0 + tx;
        __nv_bfloat16 h, l; split1(t[tx][ty + i * 8], h, l);
        g_wt_hi[n * DM + k] = h; g_wt_lo[n * DM + k] = l;
    }
}

__global__ __launch_bounds__(256)
void pos_split_kernel(const float* __restrict__ pos) {
    const int i = blockIdx.x * 256 + threadIdx.x;   // < 2048*64
    __nv_bfloat16 h, l; split1(pos[i], h, l);
    g_posh[i] = h; g_posl[i] = l;
}

// ============================================================
// Kernel 1: qkv = x @ W_qkv + b_qkv via mma.sync bf16 2-term split
// NOW: 2-stage cp.async pipeline, occ=1, 128KB smem
// stage layout: AH | AL | BH | BL (16KB each)
// ============================================================
#define QK_STAGE 65536
#define QK_SMEM_TOTAL (2 * QK_STAGE)   // 131072

__global__ __launch_bounds__(256, 1)
void qkv_tc_kernel(const float* __restrict__ bias) {
    extern __shared__ char smem[];
    const uint32_t sb = smem_to_u32(smem);
    const int tid = threadIdx.x;
    const int lane = tid & 31, wid = tid >> 5;
    const int n0 = blockIdx.x << 7, m0 = blockIdx.y << 7;
    const int mw = (wid & 1) << 6;
    const int nw = (wid >> 1) << 5;

    float acc[4][4][4];
#pragma unroll
    for (int a = 0; a < 4; a++)
#pragma unroll
        for (int b = 0; b < 4; b++)
#pragma unroll
            for (int c = 0; c < 4; c++) acc[a][b][c] = 0.f;

    const int a_r  = mw + (lane & 15);
    const int a_cb = (lane >> 4) << 4;
    const int b_r  = nw + (lane & 7) + ((lane >> 4) << 3);
    const int b_cb = (lane & 8) << 1;

    // prefetch one K-chunk (64 cols) into stage buf
    auto prefetch = [&](int chunk, int buf) {
        const int kk = chunk << 6;
        const uint32_t base = sb + buf * QK_STAGE;
#pragma unroll
        for (int j = 0; j < 4; j++) {
            const int t = tid + j * 256;
            const int r = t >> 3, g = t & 7;
            const uint32_t sw = SMEM_SWIZZLE_128B((uint32_t)(r * 128 + g * 16));
            const size_t asrc = (size_t)(m0 + r) * DM + kk + g * 8;
            const size_t bsrc = (size_t)(n0 + r) * DM + kk + g * 8;
            cpa16(base + sw,         g_a_hi + asrc);
            cpa16(base + 16384 + sw, g_a_lo + asrc);
            cpa16(base + 32768 + sw, g_wt_hi + bsrc);
            cpa16(base + 49152 + sw, g_wt_lo + bsrc);
        }
    };

    prefetch(0, 0);
    CP_COMMIT();

    for (int chunk = 0; chunk < 16; chunk++) {
        if (chunk) __syncthreads();   // readers of buf (chunk+1)&1 done (iter chunk-1)
        if (chunk < 15) prefetch(chunk + 1, (chunk + 1) & 1);
        CP_COMMIT();                  // empty group on last iter keeps accounting
        CP_WAIT1();                   // chunk's data resident
        __syncthreads();

        const uint32_t bufb = sb + (chunk & 1) * QK_STAGE;
#pragma unroll
        for (int ks = 0; ks < 4; ks++) {
            const int cb = ks << 5;
            uint32_t ah[4][4], bb[2][4];
#pragma unroll
            for (int mt = 0; mt < 4; mt++)
                ldsm4(ah[mt], bufb + SMEM_SWIZZLE_128B(
                    (uint32_t)((a_r + mt * 16) * 128 + cb + a_cb)));
#pragma unroll
            for (int p = 0; p < 2; p++)
                ldsm4(bb[p], bufb + 32768 + SMEM_SWIZZLE_128B(
                    (uint32_t)((b_r + p * 16) * 128 + cb + b_cb)));
#pragma unroll
            for (int mt = 0; mt < 4; mt++)
#pragma unroll
                for (int j = 0; j < 4; j++)
                    mma16816(acc[mt][j], ah[mt], &bb[j >> 1][(j & 1) * 2]);
            {
                uint32_t al[4][4];
#pragma unroll
                for (int mt = 0; mt < 4; mt++)
                    ldsm4(al[mt], bufb + 16384 + SMEM_SWIZZLE_128B(
                        (uint32_t)((a_r + mt * 16) * 128 + cb + a_cb)));
#pragma unroll
                for (int mt = 0; mt < 4; mt++)
#pragma unroll
                    for (int j = 0; j < 4; j++)
                        mma16816(acc[mt][j], al[mt], &bb[j >> 1][(j & 1) * 2]);
            }
#pragma unroll
            for (int p = 0; p < 2; p++)
                ldsm4(bb[p], bufb + 49152 + SMEM_SWIZZLE_128B(
                    (uint32_t)((b_r + p * 16) * 128 + cb + b_cb)));
#pragma unroll
            for (int mt = 0; mt < 4; mt++)
#pragma unroll
                for (int j = 0; j < 4; j++)
                    mma16816(acc[mt][j], ah[mt], &bb[j >> 1][(j & 1) * 2]);
        }
    }

    const int er = lane >> 2, ec = (lane & 3) << 1;
#pragma unroll
    for (int mt = 0; mt < 4; mt++) {
#pragma unroll
        for (int j = 0; j < 4; j++) {
            const int row = m0 + mw + mt * 16 + er;
            const int col = n0 + nw + j * 8 + ec;
            const float2 bv = *(const float2*)&bias[col];
            float2 lo = make_float2(acc[mt][j][0] + bv.x, acc[mt][j][1] + bv.y);
            float2 hi = make_float2(acc[mt][j][2] + bv.x, acc[mt][j][3] + bv.y);
            *(float2*)&g_qkv[(size_t)row * NCOLS + col] = lo;
            *(float2*)&g_qkv[(size_t)(row + 8) * NCOLS + col] = hi;
        }
    }
}

// ============================================================
// Kernel 2 (FUSED): split qkv -> QR/S/K bf16 hi/lo head-major
// AND V transpose -> Vt[bn][d][L] hi/lo, via smem (no g_vv pass)
// ============================================================
__global__ __launch_bounds__(256)
void splitv_kernel(const float* __restrict__ rr, const float* __restrict__ rw) {
    __shared__ float s[64][65];
    const int tid = threadIdx.x;
    const int l0 = blockIdx.x << 6;
    const int bn = blockIdx.y;
    const int b = bn >> 4, n = bn & 15;
#pragma unroll
    for (int i = 0; i < 16; i++) {
        const int idx = tid + i * 256;
        const int l = idx >> 6, d = idx & 63;
        const size_t src = (size_t)(b * LL + l0 + l) * NCOLS + n * DHEAD + d;
        const float qv = g_qkv[src];
        const float kv = g_qkv[src + DM];
        const float vv = g_qkv[src + 2 * DM];
        const int dst = (bn * LL + l0 + l) * DHEAD + d;
        __nv_bfloat16 h, lo;
        split1(qv + rr[n * DHEAD + d], h, lo);      g_qrh[dst] = h; g_qrl[dst] = lo;
        split1(qv + kv + rw[n * DHEAD + d], h, lo); g_ssh[dst] = h; g_ssl[dst] = lo;
        split1(kv, h, lo);                           g_kh[dst] = h;  g_kl[dst] = lo;
        s[l][d] = vv;
    }
    __syncthreads();
#pragma unroll
    for (int i = 0; i < 16; i++) {
        const int idx = tid + i * 256;
        const int d = idx >> 6, l = idx & 63;
        __nv_bfloat16 h, lo; split1(s[l][d], h, lo);
        const size_t o = ((size_t)bn * DHEAD + d) * LL + l0 + l;
        g_vth[o] = h; g_vtl[o] = lo;
    }
}

// ============================================================
// Kernel 3: attention, mma.sync + cp.async double-buffered pipeline
// ============================================================
#define AT_QRH 0
#define AT_QRL 8192
#define AT_SQH 16384
#define AT_SQL 24576
#define AT_PBH 32768
#define AT_PBL 40960
#define AT_T   49152            // fp32, 64 rows x pitch 132 = 33792 B
#define AT_MR  82944
#define AT_LR  83200
#define AT_FS  83456
#define AT_BUF0 83968           // per-buffer: KH|KL|VTH|VTL|POH|POL
#define AT_BUFSZ 65536
#define AT_SMEM (AT_BUF0 + 2 * AT_BUFSZ)   // 215040

__device__ __forceinline__ void at_prefetch(
    uint32_t sbuf, int tid,
    const __nv_bfloat16* kh, const __nv_bfloat16* kl,
    const __nv_bfloat16* vth, const __nv_bfloat16* vtl,
    int k0t, int pb)
{
#pragma unroll
    for (int c = 0; c < 2; c++) {
        const int idx = tid + c * 256;
        const int r = idx >> 3, g = idx & 7;
        const uint32_t sw = SMEM_SWIZZLE_128B((uint32_t)(r * 128 + g * 16));
        cpa16(sbuf + sw,         kh  + (k0t + r) * DHEAD + g * 8);
        cpa16(sbuf + 8192 + sw,  kl  + (k0t + r) * DHEAD + g * 8);
        cpa16(sbuf + 16384 + sw, vth + (size_t)r * LL + k0t + g * 8);
        cpa16(sbuf + 24576 + sw, vtl + (size_t)r * LL + k0t + g * 8);
    }
#pragma unroll
    for (int c = 0; c < 4; c++) {
        const int idx = tid + c * 256;
        const int r = idx >> 3, g = idx & 7;
        int row = pb + r; if (row > 2 * LL - 1) row = 2 * LL - 1;
        const uint32_t sw = SMEM_SWIZZLE_128B((uint32_t)(r * 128 + g * 16));
        cpa16(sbuf + 32768 + sw, g_posh + row * DHEAD + g * 8);
        cpa16(sbuf + 49152 + sw, g_posl + row * DHEAD + g * 8);
    }
}

__global__ __launch_bounds__(256, 1)
void attn_tc_kernel(float* __restrict__ out) {
    extern __shared__ char smem[];
    const uint32_t sb = smem_to_u32(smem);
    float* Ts    = (float*)(smem + AT_T);
    float* m_run = (float*)(smem + AT_MR);
    float* l_run = (float*)(smem + AT_LR);
    float* fsc   = (float*)(smem + AT_FS);

    const int tid = threadIdx.x, lane = tid & 31, wid = tid >> 5;
    const int q0 = blockIdx.x << 6;
    const int hn = blockIdx.y, hb = blockIdx.z;
    const int bn = hb * NHEAD + hn;
    const size_t hoff = (size_t)bn * LL * DHEAD;
    const __nv_bfloat16* qrh = g_qrh + hoff;
    const __nv_bfloat16* qrl = g_qrl + hoff;
    const __nv_bfloat16* ssh = g_ssh + hoff;
    const __nv_bfloat16* ssl = g_ssl + hoff;
    const __nv_bfloat16* kh  = g_kh + hoff;
    const __nv_bfloat16* kl  = g_kl + hoff;
    const __nv_bfloat16* vth = g_vth + hoff;   // [d][L]
    const __nv_bfloat16* vtl = g_vtl + hoff;

    const int mwq = (wid & 3) << 4;
    const int ng  = wid >> 2;
    const int aRow = lane & 15, aCol = (lane >> 4) << 4;
    const int bRow = (lane & 7) + ((lane >> 4) << 3), bCol = (lane & 8) << 1;
    const int er = lane >> 2, ec = (lane & 3) << 1;

    // prologue: QR/S copies + tile0 prefetch -> group 1
#pragma unroll
    for (int c = 0; c < 2; c++) {
        const int idx = tid + c * 256;
        const int r = idx >> 3, g = idx & 7;
        const uint32_t sw = SMEM_SWIZZLE_128B((uint32_t)(r * 128 + g * 16));
        const int so = (q0 + r) * DHEAD + g * 8;
        cpa16(sb + AT_QRH + sw, qrh + so);
        cpa16(sb + AT_QRL + sw, qrl + so);
        cpa16(sb + AT_SQH + sw, ssh + so);
        cpa16(sb + AT_SQL + sw, ssl + so);
    }
    at_prefetch(sb + AT_BUF0, tid, kh, kl, vth, vtl, 0, LL - q0 - 63);
    CP_COMMIT();

    if (tid < 64) { m_run[tid] = -1e30f; l_run[tid] = 0.f; }

    float accO[4][4];
#pragma unroll
    for (int j = 0; j < 4; j++)
#pragma unroll
        for (int c = 0; c < 4; c++) accO[j][c] = 0.f;

    for (int kt = 0; kt < 16; kt++) {
        __syncthreads();    // all warps done reading buf (kt+1)&1 from iter kt-1
        if (kt < 15)
            at_prefetch(sb + AT_BUF0 + ((kt + 1) & 1) * AT_BUFSZ, tid,
                        kh, kl, vth, vtl, (kt + 1) << 6,
                        LL + ((kt + 1) << 6) - q0 - 63);
        CP_COMMIT();        // empty group on last iter keeps accounting
        CP_WAIT1();         // tile kt data resident
        __syncthreads();

        const uint32_t bufb = sb + AT_BUF0 + (kt & 1) * AT_BUFSZ;

        // ---- AC = QR · K^T (64x64) into regs; T = Sq · P127^T (64x128) -> Ts ----
        float acc[4][4];
#pragma unroll
        for (int j = 0; j < 4; j++)
#pragma unroll
            for (int c = 0; c < 4; c++) acc[j][c] = 0.f;
#pragma unroll
        for (int ks = 0; ks < 4; ks++) {
            const int cb = ks << 5;
            uint32_t ah[4], al[4], bh[2][4];
            ldsm4(ah, sb + AT_QRH + SMEM_SWIZZLE_128B(
                (uint32_t)((mwq + aRow) * 128 + cb + aCol)));
            ldsm4(al, sb + AT_QRL + SMEM_SWIZZLE_128B(
                (uint32_t)((mwq + aRow) * 128 + cb + aCol)));
#pragma unroll
            for (int p = 0; p < 2; p++)
                ldsm4(bh[p], bufb + SMEM_SWIZZLE_128B(
                    (uint32_t)((ng * 32 + p * 16 + bRow) * 128 + cb + bCol)));
#pragma unroll
            for (int j = 0; j < 4; j++)
                mma16816(acc[j], ah, &bh[j >> 1][(j & 1) * 2]);
#pragma unroll
            for (int j = 0; j < 4; j++)
                mma16816(acc[j], al, &bh[j >> 1][(j & 1) * 2]);
#pragma unroll
            for (int p = 0; p < 2; p++)
                ldsm4(bh[p], bufb + 8192 + SMEM_SWIZZLE_128B(
                    (uint32_t)((ng * 32 + p * 16 + bRow) * 128 + cb + bCol)));
#pragma unroll
            for (int j = 0; j < 4; j++)
                mma16816(acc[j], ah, &bh[j >> 1][(j & 1) * 2]);
        }
        {
            float accT[8][4];
#pragma unroll
            for (int j = 0; j < 8; j++)
#pragma unroll
                for (int c = 0; c < 4; c++) accT[j][c] = 0.f;
#pragma unroll
            for (int ks = 0; ks < 4; ks++) {
                const int cb = ks << 5;
                uint32_t sh[4], sl[4], pf[4][4];
                ldsm4(sh, sb + AT_SQH + SMEM_SWIZZLE_128B(
                    (uint32_t)((mwq + aRow) * 128 + cb + aCol)));
                ldsm4(sl, sb + AT_SQL + SMEM_SWIZZLE_128B(
                    (uint32_t)((mwq + aRow) * 128 + cb + aCol)));
#pragma unroll
                for (int p = 0; p < 4; p++)
                    ldsm4(pf[p], bufb + 32768 + SMEM_SWIZZLE_128B(
                        (uint32_t)((ng * 64 + p * 16 + bRow) * 128 + cb + bCol)));
#pragma unroll
                for (int j = 0; j < 8; j++)
                    mma16816(accT[j], sh, &pf[j >> 1][(j & 1) * 2]);
#pragma unroll
                for (int j = 0; j < 8; j++)
                    mma16816(accT[j], sl, &pf[j >> 1][(j & 1) * 2]);
#pragma unroll
                for (int p = 0; p < 4; p++)
                    ldsm4(pf[p], bufb + 49152 + SMEM_SWIZZLE_128B(
                        (uint32_t)((ng * 64 + p * 16 + bRow) * 128 + cb + bCol)));
#pragma unroll
                for (int j = 0; j < 8; j++)
                    mma16816(accT[j], sh, &pf[j >> 1][(j & 1) * 2]);
            }
#pragma unroll
            for (int j = 0; j < 8; j++) {
                const int col = ng * 64 + j * 8 + ec;
                *(float2*)&Ts[(mwq + er) * 132 + col] =
                    make_float2(accT[j][0], accT[j][1]);
                *(float2*)&Ts[(mwq + er + 8) * 132 + col] =
                    make_float2(accT[j][2], accT[j][3]);
            }
        }
        __syncthreads();

        // ---- fold AC into Ts at gathered positions ----
#pragma unroll
        for (int j = 0; j < 4; j++) {
            const int ki = ng * 32 + j * 8 + ec;
            const int r0 = mwq + er, r1 = r0 + 8;
            Ts[r0 * 132 + 63 - r0 + ki]     += acc[j][0];
            Ts[r0 * 132 + 63 - r0 + ki + 1] += acc[j][1];
            Ts[r1 * 132 + 63 - r1 + ki]     += acc[j][2];
            Ts[r1 * 132 + 63 - r1 + ki + 1] += acc[j][3];
        }
        __syncthreads();

        // ---- softmax + probs -> bf16 hi/lo ----
        {
            const int row = tid >> 2, sub = tid & 3;
            const int c0 = sub << 4;
            const float* tp = &Ts[row * 132 + 63 - row + c0];
            float v[16];
#pragma unroll
            for (int j = 0; j < 16; j++) v[j] = tp[j] * 0.125f;
            float mx = v[0];
#pragma unroll
            for (int j = 1; j < 16; j++) mx = fmaxf(mx, v[j]);
            mx = fmaxf(mx, __shfl_xor_sync(0xffffffffu, mx, 1));
            mx = fmaxf(mx, __shfl_xor_sync(0xffffffffu, mx, 2));
            const float mold = m_run[row];
            const float mnew = fmaxf(mold, mx);
            const float fac = __expf(mold - mnew);
            float s = 0.f;
#pragma unroll
            for (int j = 0; j < 16; j++) { v[j] = __expf(v[j] - mnew); s += v[j]; }
            uint4 h0, l0, h1, l1;
            split8(v, h0, l0);
            split8(v + 8, h1, l1);
            const uint32_t sw0 = SMEM_SWIZZLE_128B((uint32_t)(row * 128 + sub * 32));
            const uint32_t sw1 = SMEM_SWIZZLE_128B((uint32_t)(row * 128 + sub * 32 + 16));
            *(uint4*)(smem + AT_PBH + sw0) = h0;
            *(uint4*)(smem + AT_PBH + sw1) = h1;
            *(uint4*)(smem + AT_PBL + sw0) = l0;
            *(uint4*)(smem + AT_PBL + sw1) = l1;
            s += __shfl_xor_sync(0xffffffffu, s, 1);
            s += __shfl_xor_sync(0xffffffffu, s, 2);
            if (sub == 0) {
                l_run[row] = l_run[row] * fac + s;
                m_run[row] = mnew;
                fsc[row] = fac;
            }
        }
        __syncthreads();

        // ---- O rescale + PV (3 chains) ----
        {
            const float f0 = fsc[mwq + er], f1 = fsc[mwq + er + 8];
#pragma unroll
            for (int j = 0; j < 4; j++) {
                accO[j][0] *= f0; accO[j][1] *= f0;
                accO[j][2] *= f1; accO[j][3] *= f1;
            }
#pragma unroll
            for (int ks = 0; ks < 4; ks++) {
                const int cb = ks << 5;
                uint32_t pah[4], pal[4], vf[2][4];
                ldsm4(pah, sb + AT_PBH + SMEM_SWIZZLE_128B(
                    (uint32_t)((mwq + aRow) * 128 + cb + aCol)));
                ldsm4(pal, sb + AT_PBL + SMEM_SWIZZLE_128B(
                    (uint32_t)((mwq + aRow) * 128 + cb + aCol)));
#pragma unroll
                for (int p = 0; p < 2; p++)
                    ldsm4(vf[p], bufb + 16384 + SMEM_SWIZZLE_128B(
                        (uint32_t)((ng * 32 + p * 16 + bRow) * 128 + cb + bCol)));
#pragma unroll
                for (int j = 0; j < 4; j++)
                    mma16816(accO[j], pah, &vf[j >> 1][(j & 1) * 2]);
#pragma unroll
                for (int j = 0; j < 4; j++)
                    mma16816(accO[j], pal, &vf[j >> 1][(j & 1) * 2]);
#pragma unroll
                for (int p = 0; p < 2; p++)
                    ldsm4(vf[p], bufb + 24576 + SMEM_SWIZZLE_128B(
                        (uint32_t)((ng * 32 + p * 16 + bRow) * 128 + cb + bCol)));
#pragma unroll
                for (int j = 0; j < 4; j++)
                    mma16816(accO[j], pah, &vf[j >> 1][(j & 1) * 2]);
            }
        }
    }

    // finalize: out[hb, q, hn*64 + d] = O / l
    {
        const float inv0 = 1.0f / l_run[mwq + er];
        const float inv1 = 1.0f / l_run[mwq + er + 8];
        const int r0 = q0 + mwq + er;
#pragma unroll
        for (int j = 0; j < 4; j++) {
            const int col = hn * 64 + ng * 32 + j * 8 + ec;
            *(float2*)&out[(size_t)(hb * LL + r0) * DM + col] =
                make_float2(accO[j][0] * inv0, accO[j][1] * inv0);
            *(float2*)&out[(size_t)(hb * LL + r0 + 8) * DM + col] =
                make_float2(accO[j][2] * inv1, accO[j][3] * inv1);
        }
    }
}

// ============================================================
extern "C" void kernel_launch(void* const* d_in, const int* in_sizes, int n_in,
                              void* d_out, int out_size) {
    const float* x   = (const float*)d_in[0];
    const float* pos = (const float*)d_in[1];
    const float* W   = (const float*)d_in[2];
    const float* bqk = (const float*)d_in[3];
    const float* rr  = (const float*)d_in[4];
    const float* rw  = (const float*)d_in[5];
    float* out = (float*)d_out;

    cudaFuncSetAttribute(qkv_tc_kernel,
                         cudaFuncAttributeMaxDynamicSharedMemorySize, QK_SMEM_TOTAL);
    cudaFuncSetAttribute(attn_tc_kernel,
                         cudaFuncAttributeMaxDynamicSharedMemorySize, AT_SMEM);

    conv_x_kernel<<<(MROWS * DM) / 256, 256>>>(x);
    conv_w_kernel<<<dim3(NCOLS / 32, DM / 32), dim3(32, 8)>>>(W);
    pos_split_kernel<<<(2 * LL * DHEAD) / 256, 256>>>(pos);
    qkv_tc_kernel<<<dim3(NCOLS / 128, MROWS / 128), 256, QK_SMEM_TOTAL>>>(bqk);
    splitv_kernel<<<dim3(LL / 64, BB * NHEAD), 256>>>(rr, rw);
    attn_tc_kernel<<<dim3(LL / 64, NHEAD, BB), 256, AT_SMEM>>>(out);
}

// round 17
// speedup vs baseline: 3.3757x; 1.0382x over previous
#include <cuda_runtime.h>
#include <cuda_bf16.h>
#include <cstdint>

#define BB 4
#define LL 1024
#define DM 1024
#define NHEAD 16
#define DHEAD 64
#define MROWS (BB * LL)      // 4096
#define NCOLS (3 * DM)       // 3072
#define NBH (BB * NHEAD * LL * DHEAD)   // 4M elements
#define NSM 152
#define QK_TILES ((NCOLS / 128) * (MROWS / 128))   // 768

// ---- scratch (static device globals; no runtime allocation) ----
__device__ float g_qkv[MROWS * NCOLS];          // 48 MB
// bf16 hi/lo operands for attention
__device__ __nv_bfloat16 g_qrh[NBH], g_qrl[NBH];
__device__ __nv_bfloat16 g_ssh[NBH], g_ssl[NBH];
__device__ __nv_bfloat16 g_kh[NBH],  g_kl[NBH];
__device__ __nv_bfloat16 g_vth[NBH], g_vtl[NBH];     // [bn][d][L]
__device__ __nv_bfloat16 g_posh[2 * LL * DHEAD], g_posl[2 * LL * DHEAD];
// bf16 split operands for mma.sync qkv GEMM
__device__ __nv_bfloat16 g_a_hi[MROWS * DM];
__device__ __nv_bfloat16 g_a_lo[MROWS * DM];
__device__ __nv_bfloat16 g_wt_hi[NCOLS * DM];
__device__ __nv_bfloat16 g_wt_lo[NCOLS * DM];

// ============================================================
// helpers
// ============================================================
__device__ __forceinline__ uint32_t smem_to_u32(const void* p) {
    uint32_t a;
    asm("{ .reg .u64 t; cvta.to.shared.u64 t, %1; cvt.u32.u64 %0, t; }"
        : "=r"(a) : "l"(p));
    return a;
}
#define SMEM_SWIZZLE_128B(byte_offset) \
    ((byte_offset) ^ (((byte_offset) >> 3) & 0x70))

__device__ __forceinline__ void ldsm4(uint32_t* r, uint32_t addr) {
    asm volatile("ldmatrix.sync.aligned.m8n8.x4.shared.b16 {%0,%1,%2,%3}, [%4];"
        : "=r"(r[0]), "=r"(r[1]), "=r"(r[2]), "=r"(r[3]) : "r"(addr));
}
__device__ __forceinline__ void mma16816(float* c, const uint32_t* a, const uint32_t* b) {
    asm volatile(
        "mma.sync.aligned.m16n8k16.row.col.f32.bf16.bf16.f32 "
        "{%0,%1,%2,%3}, {%4,%5,%6,%7}, {%8,%9}, {%0,%1,%2,%3};"
        : "+f"(c[0]), "+f"(c[1]), "+f"(c[2]), "+f"(c[3])
        : "r"(a[0]), "r"(a[1]), "r"(a[2]), "r"(a[3]), "r"(b[0]), "r"(b[1]));
}
__device__ __forceinline__ void cpa16(uint32_t dst, const void* src) {
    asm volatile("cp.async.cg.shared.global [%0], [%1], 16;"
        :: "r"(dst), "l"(src) : "memory");
}
#define CP_COMMIT() asm volatile("cp.async.commit_group;" ::: "memory")
#define CP_WAIT1()  asm volatile("cp.async.wait_group 1;" ::: "memory")

// split 8 fp32 into 8 bf16 hi + 8 bf16 lo, packed as uint4 each
__device__ __forceinline__ void split8(const float* v, uint4& h4, uint4& l4) {
    uint32_t h[4], l[4];
#pragma unroll
    for (int i = 0; i < 4; i++) {
        float x = v[2 * i], y = v[2 * i + 1];
        __nv_bfloat16 hx = __float2bfloat16(x), hy = __float2bfloat16(y);
        float rx = x - __bfloat162float(hx), ry = y - __bfloat162float(hy);
        __nv_bfloat16 lx = __float2bfloat16(rx), ly = __float2bfloat16(ry);
        h[i] = (uint32_t)(*(uint16_t*)&hx) | ((uint32_t)(*(uint16_t*)&hy) << 16);
        l[i] = (uint32_t)(*(uint16_t*)&lx) | ((uint32_t)(*(uint16_t*)&ly) << 16);
    }
    h4 = make_uint4(h[0], h[1], h[2], h[3]);
    l4 = make_uint4(l[0], l[1], l[2], l[3]);
}
__device__ __forceinline__ void split1(float v, __nv_bfloat16& h, __nv_bfloat16& l) {
    h = __float2bfloat16(v);
    l = __float2bfloat16(v - __bfloat162float(h));
}

// ============================================================
// Conversion kernels
// ============================================================
__global__ __launch_bounds__(256)
void conv_x_kernel(const float* __restrict__ x) {
    const int i = blockIdx.x * 256 + threadIdx.x;
    __nv_bfloat16 h, l; split1(x[i], h, l);
    g_a_hi[i] = h; g_a_lo[i] = l;
}

__global__ __launch_bounds__(256)
void conv_w_kernel(const float* __restrict__ W) {
    __shared__ float t[32][33];
    const int tx = threadIdx.x, ty = threadIdx.y;
    const int n0 = blockIdx.x * 32, k0 = blockIdx.y * 32;
#pragma unroll
    for (int i = 0; i < 4; i++)
        t[ty + i * 8][tx] = W[(k0 + ty + i * 8) * NCOLS + n0 + tx];
    __syncthreads();
#pragma unroll
    for (int i = 0; i < 4; i++) {
        const int n = n0 + ty + i * 8;
        const int k = k0 + tx;
        __nv_bfloat16 h, l; split1(t[tx][ty + i * 8], h, l);
        g_wt_hi[n * DM + k] = h; g_wt_lo[n * DM + k] = l;
    }
}

__global__ __launch_bounds__(256)
void pos_split_kernel(const float* __restrict__ pos) {
    const int i = blockIdx.x * 256 + threadIdx.x;   // < 2048*64
    __nv_bfloat16 h, l; split1(pos[i], h, l);
    g_posh[i] = h; g_posl[i] = l;
}

// ============================================================
// Kernel 1: qkv = x @ W_qkv + b_qkv via mma.sync bf16 2-term split
// PERSISTENT: grid=NSM, each CTA loops over tiles (no wave tail).
// 2-stage cp.async pipeline per tile, 128KB smem.
// NOTE: chunk-loop top sync is UNCONDITIONAL — it orders tile t's
// chunk-15 buf1 readers before tile t+1's chunk-0 buf1 prefetch.
// ============================================================
#define QK_STAGE 65536
#define QK_SMEM_TOTAL (2 * QK_STAGE)   // 131072

__global__ __launch_bounds__(256, 1)
void qkv_tc_kernel(const float* __restrict__ bias) {
    extern __shared__ char smem[];
    const uint32_t sb = smem_to_u32(smem);
    const int tid = threadIdx.x;
    const int lane = tid & 31, wid = tid >> 5;
    const int mw = (wid & 1) << 6;
    const int nw = (wid >> 1) << 5;

    const int a_r  = mw + (lane & 15);
    const int a_cb = (lane >> 4) << 4;
    const int b_r  = nw + (lane & 7) + ((lane >> 4) << 3);
    const int b_cb = (lane & 8) << 1;
    const int er = lane >> 2, ec = (lane & 3) << 1;

    auto prefetch = [&](int chunk, int buf, int m0, int n0) {
        const int kk = chunk << 6;
        const uint32_t base = sb + buf * QK_STAGE;
#pragma unroll
        for (int j = 0; j < 4; j++) {
            const int t = tid + j * 256;
            const int r = t >> 3, g = t & 7;
            const uint32_t sw = SMEM_SWIZZLE_128B((uint32_t)(r * 128 + g * 16));
            const size_t asrc = (size_t)(m0 + r) * DM + kk + g * 8;
            const size_t bsrc = (size_t)(n0 + r) * DM + kk + g * 8;
            cpa16(base + sw,         g_a_hi + asrc);
            cpa16(base + 16384 + sw, g_a_lo + asrc);
            cpa16(base + 32768 + sw, g_wt_hi + bsrc);
            cpa16(base + 49152 + sw, g_wt_lo + bsrc);
        }
    };

    for (int t = blockIdx.x; t < QK_TILES; t += NSM) {
        const int n0 = (t % 24) << 7;
        const int m0 = (t / 24) << 7;

        float acc[4][4][4];
#pragma unroll
        for (int a = 0; a < 4; a++)
#pragma unroll
            for (int b = 0; b < 4; b++)
#pragma unroll
                for (int c = 0; c < 4; c++) acc[a][b][c] = 0.f;

        prefetch(0, 0, m0, n0);
        CP_COMMIT();

        for (int chunk = 0; chunk < 16; chunk++) {
            __syncthreads();   // UNCONDITIONAL: also guards tile-boundary buf reuse
            if (chunk < 15) prefetch(chunk + 1, (chunk + 1) & 1, m0, n0);
            CP_COMMIT();                  // empty group on last iter
            CP_WAIT1();
            __syncthreads();

            const uint32_t bufb = sb + (chunk & 1) * QK_STAGE;
#pragma unroll
            for (int ks = 0; ks < 4; ks++) {
                const int cb = ks << 5;
                uint32_t ah[4][4], bb[2][4];
#pragma unroll
                for (int mt = 0; mt < 4; mt++)
                    ldsm4(ah[mt], bufb + SMEM_SWIZZLE_128B(
                        (uint32_t)((a_r + mt * 16) * 128 + cb + a_cb)));
#pragma unroll
                for (int p = 0; p < 2; p++)
                    ldsm4(bb[p], bufb + 32768 + SMEM_SWIZZLE_128B(
                        (uint32_t)((b_r + p * 16) * 128 + cb + b_cb)));
#pragma unroll
                for (int mt = 0; mt < 4; mt++)
#pragma unroll
                    for (int j = 0; j < 4; j++)
                        mma16816(acc[mt][j], ah[mt], &bb[j >> 1][(j & 1) * 2]);
                {
                    uint32_t al[4][4];
#pragma unroll
                    for (int mt = 0; mt < 4; mt++)
                        ldsm4(al[mt], bufb + 16384 + SMEM_SWIZZLE_128B(
                            (uint32_t)((a_r + mt * 16) * 128 + cb + a_cb)));
#pragma unroll
                    for (int mt = 0; mt < 4; mt++)
#pragma unroll
                        for (int j = 0; j < 4; j++)
                            mma16816(acc[mt][j], al[mt], &bb[j >> 1][(j & 1) * 2]);
                }
#pragma unroll
                for (int p = 0; p < 2; p++)
                    ldsm4(bb[p], bufb + 49152 + SMEM_SWIZZLE_128B(
                        (uint32_t)((b_r + p * 16) * 128 + cb + b_cb)));
#pragma unroll
                for (int mt = 0; mt < 4; mt++)
#pragma unroll
                    for (int j = 0; j < 4; j++)
                        mma16816(acc[mt][j], ah[mt], &bb[j >> 1][(j & 1) * 2]);
            }
        }

#pragma unroll
        for (int mt = 0; mt < 4; mt++) {
#pragma unroll
            for (int j = 0; j < 4; j++) {
                const int row = m0 + mw + mt * 16 + er;
                const int col = n0 + nw + j * 8 + ec;
                const float2 bv = *(const float2*)&bias[col];
                float2 lo = make_float2(acc[mt][j][0] + bv.x, acc[mt][j][1] + bv.y);
                float2 hi = make_float2(acc[mt][j][2] + bv.x, acc[mt][j][3] + bv.y);
                *(float2*)&g_qkv[(size_t)row * NCOLS + col] = lo;
                *(float2*)&g_qkv[(size_t)(row + 8) * NCOLS + col] = hi;
            }
        }
    }
}

// ============================================================
// Kernel 2 (FUSED): split qkv -> QR/S/K bf16 hi/lo head-major
// AND V transpose -> Vt[bn][d][L] hi/lo, via smem
// ============================================================
__global__ __launch_bounds__(256)
void splitv_kernel(const float* __restrict__ rr, const float* __restrict__ rw) {
    __shared__ float s[64][65];
    const int tid = threadIdx.x;
    const int l0 = blockIdx.x << 6;
    const int bn = blockIdx.y;
    const int b = bn >> 4, n = bn & 15;
#pragma unroll
    for (int i = 0; i < 16; i++) {
        const int idx = tid + i * 256;
        const int l = idx >> 6, d = idx & 63;
        const size_t src = (size_t)(b * LL + l0 + l) * NCOLS + n * DHEAD + d;
        const float qv = g_qkv[src];
        const float kv = g_qkv[src + DM];
        const float vv = g_qkv[src + 2 * DM];
        const int dst = (bn * LL + l0 + l) * DHEAD + d;
        __nv_bfloat16 h, lo;
        split1(qv + rr[n * DHEAD + d], h, lo);      g_qrh[dst] = h; g_qrl[dst] = lo;
        split1(qv + kv + rw[n * DHEAD + d], h, lo); g_ssh[dst] = h; g_ssl[dst] = lo;
        split1(kv, h, lo);                           g_kh[dst] = h;  g_kl[dst] = lo;
        s[l][d] = vv;
    }
    __syncthreads();
#pragma unroll
    for (int i = 0; i < 16; i++) {
        const int idx = tid + i * 256;
        const int d = idx >> 6, l = idx & 63;
        __nv_bfloat16 h, lo; split1(s[l][d], h, lo);
        const size_t o = ((size_t)bn * DHEAD + d) * LL + l0 + l;
        g_vth[o] = h; g_vtl[o] = lo;
    }
}

// ============================================================
// Kernel 3: attention, mma.sync + cp.async double-buffered pipeline
// T-GEMM computes only the 5 needed 16-col tiles per row group
// (gather window cols [48-mwq, 126-mwq]).
// ============================================================
#define AT_QRH 0
#define AT_QRL 8192
#define AT_SQH 16384
#define AT_SQL 24576
#define AT_PBH 32768
#define AT_PBL 40960
#define AT_T   49152            // fp32, 64 rows x pitch 132 = 33792 B
#define AT_MR  82944
#define AT_LR  83200
#define AT_FS  83456
#define AT_BUF0 83968           // per-buffer: KH|KL|VTH|VTL|POH|POL
#define AT_BUFSZ 65536
#define AT_SMEM (AT_BUF0 + 2 * AT_BUFSZ)   // 215040

__device__ __forceinline__ void at_prefetch(
    uint32_t sbuf, int tid,
    const __nv_bfloat16* kh, const __nv_bfloat16* kl,
    const __nv_bfloat16* vth, const __nv_bfloat16* vtl,
    int k0t, int pb)
{
#pragma unroll
    for (int c = 0; c < 2; c++) {
        const int idx = tid + c * 256;
        const int r = idx >> 3, g = idx & 7;
        const uint32_t sw = SMEM_SWIZZLE_128B((uint32_t)(r * 128 + g * 16));
        cpa16(sbuf + sw,         kh  + (k0t + r) * DHEAD + g * 8);
        cpa16(sbuf + 8192 + sw,  kl  + (k0t + r) * DHEAD + g * 8);
        cpa16(sbuf + 16384 + sw, vth + (size_t)r * LL + k0t + g * 8);
        cpa16(sbuf + 24576 + sw, vtl + (size_t)r * LL + k0t + g * 8);
    }
#pragma unroll
    for (int c = 0; c < 4; c++) {
        const int idx = tid + c * 256;
        const int r = idx >> 3, g = idx & 7;
        int row = pb + r; if (row > 2 * LL - 1) row = 2 * LL - 1;
        const uint32_t sw = SMEM_SWIZZLE_128B((uint32_t)(r * 128 + g * 16));
        cpa16(sbuf + 32768 + sw, g_posh + row * DHEAD + g * 8);
        cpa16(sbuf + 49152 + sw, g_posl + row * DHEAD + g * 8);
    }
}

__global__ __launch_bounds__(256, 1)
void attn_tc_kernel(float* __restrict__ out) {
    extern __shared__ char smem[];
    const uint32_t sb = smem_to_u32(smem);
    float* Ts    = (float*)(smem + AT_T);
    float* m_run = (float*)(smem + AT_MR);
    float* l_run = (float*)(smem + AT_LR);
    float* fsc   = (float*)(smem + AT_FS);

    const int tid = threadIdx.x, lane = tid & 31, wid = tid >> 5;
    const int q0 = blockIdx.x << 6;
    const int hn = blockIdx.y, hb = blockIdx.z;
    const int bn = hb * NHEAD + hn;
    const size_t hoff = (size_t)bn * LL * DHEAD;
    const __nv_bfloat16* qrh = g_qrh + hoff;
    const __nv_bfloat16* qrl = g_qrl + hoff;
    const __nv_bfloat16* ssh = g_ssh + hoff;
    const __nv_bfloat16* ssl = g_ssl + hoff;
    const __nv_bfloat16* kh  = g_kh + hoff;
    const __nv_bfloat16* kl  = g_kl + hoff;
    const __nv_bfloat16* vth = g_vth + hoff;   // [d][L]
    const __nv_bfloat16* vtl = g_vtl + hoff;

    const int mwq = (wid & 3) << 4;
    const int ng  = wid >> 2;
    const int aRow = lane & 15, aCol = (lane >> 4) << 4;
    const int bRow = (lane & 7) + ((lane >> 4) << 3), bCol = (lane & 8) << 1;
    const int er = lane >> 2, ec = (lane & 3) << 1;
    // windowed T tiles: row-group window starts at col 48-mwq = (3-mwq/16)*16
    const int s0 = 3 - (mwq >> 4);
    const int tb = s0 + (ng ? 3 : 0);      // first tile for this warp
    const int tcnt = ng ? 2 : 3;           // tiles this warp computes

    // prologue: QR/S copies + tile0 prefetch
#pragma unroll
    for (int c = 0; c < 2; c++) {
        const int idx = tid + c * 256;
        const int r = idx >> 3, g = idx & 7;
        const uint32_t sw = SMEM_SWIZZLE_128B((uint32_t)(r * 128 + g * 16));
        const int so = (q0 + r) * DHEAD + g * 8;
        cpa16(sb + AT_QRH + sw, qrh + so);
        cpa16(sb + AT_QRL + sw, qrl + so);
        cpa16(sb + AT_SQH + sw, ssh + so);
        cpa16(sb + AT_SQL + sw, ssl + so);
    }
    at_prefetch(sb + AT_BUF0, tid, kh, kl, vth, vtl, 0, LL - q0 - 63);
    CP_COMMIT();

    if (tid < 64) { m_run[tid] = -1e30f; l_run[tid] = 0.f; }

    float accO[4][4];
#pragma unroll
    for (int j = 0; j < 4; j++)
#pragma unroll
        for (int c = 0; c < 4; c++) accO[j][c] = 0.f;

    for (int kt = 0; kt < 16; kt++) {
        __syncthreads();
        if (kt < 15)
            at_prefetch(sb + AT_BUF0 + ((kt + 1) & 1) * AT_BUFSZ, tid,
                        kh, kl, vth, vtl, (kt + 1) << 6,
                        LL + ((kt + 1) << 6) - q0 - 63);
        CP_COMMIT();
        CP_WAIT1();
        __syncthreads();

        const uint32_t bufb = sb + AT_BUF0 + (kt & 1) * AT_BUFSZ;

        // ---- AC = QR · K^T (64x64) into regs ----
        float acc[4][4];
#pragma unroll
        for (int j = 0; j < 4; j++)
#pragma unroll
            for (int c = 0; c < 4; c++) acc[j][c] = 0.f;
#pragma unroll
        for (int ks = 0; ks < 4; ks++) {
            const int cb = ks << 5;
            uint32_t ah[4], al[4], bh[2][4];
            ldsm4(ah, sb + AT_QRH + SMEM_SWIZZLE_128B(
                (uint32_t)((mwq + aRow) * 128 + cb + aCol)));
            ldsm4(al, sb + AT_QRL + SMEM_SWIZZLE_128B(
                (uint32_t)((mwq + aRow) * 128 + cb + aCol)));
#pragma unroll
            for (int p = 0; p < 2; p++)
                ldsm4(bh[p], bufb + SMEM_SWIZZLE_128B(
                    (uint32_t)((ng * 32 + p * 16 + bRow) * 128 + cb + bCol)));
#pragma unroll
            for (int j = 0; j < 4; j++)
                mma16816(acc[j], ah, &bh[j >> 1][(j & 1) * 2]);
#pragma unroll
            for (int j = 0; j < 4; j++)
                mma16816(acc[j], al, &bh[j >> 1][(j & 1) * 2]);
#pragma unroll
            for (int p = 0; p < 2; p++)
                ldsm4(bh[p], bufb + 8192 + SMEM_SWIZZLE_128B(
                    (uint32_t)((ng * 32 + p * 16 + bRow) * 128 + cb + bCol)));
#pragma unroll
            for (int j = 0; j < 4; j++)
                mma16816(acc[j], ah, &bh[j >> 1][(j & 1) * 2]);
        }
        // ---- T = Sq · P^T, windowed: only tiles tb..tb+tcnt-1 ----
        {
            float accT[6][4];
#pragma unroll
            for (int j = 0; j < 6; j++)
#pragma unroll
                for (int c = 0; c < 4; c++) accT[j][c] = 0.f;
#pragma unroll
            for (int ks = 0; ks < 4; ks++) {
                const int cb = ks << 5;
                uint32_t sh[4], sl[4], pf[3][4];
                ldsm4(sh, sb + AT_SQH + SMEM_SWIZZLE_128B(
                    (uint32_t)((mwq + aRow) * 128 + cb + aCol)));
                ldsm4(sl, sb + AT_SQL + SMEM_SWIZZLE_128B(
                    (uint32_t)((mwq + aRow) * 128 + cb + aCol)));
#pragma unroll
                for (int p = 0; p < 3; p++)
                    if (p < tcnt)
                        ldsm4(pf[p], bufb + 32768 + SMEM_SWIZZLE_128B(
                            (uint32_t)(((tb + p) * 16 + bRow) * 128 + cb + bCol)));
#pragma unroll
                for (int p = 0; p < 3; p++)
                    if (p < tcnt)
#pragma unroll
                        for (int jj = 0; jj < 2; jj++)
                            mma16816(accT[p * 2 + jj], sh, &pf[p][jj * 2]);
#pragma unroll
                for (int p = 0; p < 3; p++)
                    if (p < tcnt)
#pragma unroll
                        for (int jj = 0; jj < 2; jj++)
                            mma16816(accT[p * 2 + jj], sl, &pf[p][jj * 2]);
#pragma unroll
                for (int p = 0; p < 3; p++)
                    if (p < tcnt)
                        ldsm4(pf[p], bufb + 49152 + SMEM_SWIZZLE_128B(
                            (uint32_t)(((tb + p) * 16 + bRow) * 128 + cb + bCol)));
#pragma unroll
                for (int p = 0; p < 3; p++)
                    if (p < tcnt)
#pragma unroll
                        for (int jj = 0; jj < 2; jj++)
                            mma16816(accT[p * 2 + jj], sh, &pf[p][jj * 2]);
            }
#pragma unroll
            for (int p = 0; p < 3; p++)
                if (p < tcnt)
#pragma unroll
                    for (int jj = 0; jj < 2; jj++) {
                        const int col = (tb + p) * 16 + jj * 8 + ec;
                        *(float2*)&Ts[(mwq + er) * 132 + col] =
                            make_float2(accT[p * 2 + jj][0], accT[p * 2 + jj][1]);
                        *(float2*)&Ts[(mwq + er + 8) * 132 + col] =
                            make_float2(accT[p * 2 + jj][2], accT[p * 2 + jj][3]);
                    }
        }
        __syncthreads();

        // ---- fold AC into Ts at gathered positions ----
#pragma unroll
        for (int j = 0; j < 4; j++) {
            const int ki = ng * 32 + j * 8 + ec;
            const int r0 = mwq + er, r1 = r0 + 8;
            Ts[r0 * 132 + 63 - r0 + ki]     += acc[j][0];
            Ts[r0 * 132 + 63 - r0 + ki + 1] += acc[j][1];
            Ts[r1 * 132 + 63 - r1 + ki]     += acc[j][2];
            Ts[r1 * 132 + 63 - r1 + ki + 1] += acc[j][3];
        }
        __syncthreads();

        // ---- softmax + probs -> bf16 hi/lo ----
        {
            const int row = tid >> 2, sub = tid & 3;
            const int c0 = sub << 4;
            const float* tp = &Ts[row * 132 + 63 - row + c0];
            float v[16];
#pragma unroll
            for (int j = 0; j < 16; j++) v[j] = tp[j] * 0.125f;
            float mx = v[0];
#pragma unroll
            for (int j = 1; j < 16; j++) mx = fmaxf(mx, v[j]);
            mx = fmaxf(mx, __shfl_xor_sync(0xffffffffu, mx, 1));
            mx = fmaxf(mx, __shfl_xor_sync(0xffffffffu, mx, 2));
            const float mold = m_run[row];
            const float mnew = fmaxf(mold, mx);
            const float fac = __expf(mold - mnew);
            float s = 0.f;
#pragma unroll
            for (int j = 0; j < 16; j++) { v[j] = __expf(v[j] - mnew); s += v[j]; }
            uint4 h0, l0, h1, l1;
            split8(v, h0, l0);
            split8(v + 8, h1, l1);
            const uint32_t sw0 = SMEM_SWIZZLE_128B((uint32_t)(row * 128 + sub * 32));
            const uint32_t sw1 = SMEM_SWIZZLE_128B((uint32_t)(row * 128 + sub * 32 + 16));
            *(uint4*)(smem + AT_PBH + sw0) = h0;
            *(uint4*)(smem + AT_PBH + sw1) = h1;
            *(uint4*)(smem + AT_PBL + sw0) = l0;
            *(uint4*)(smem + AT_PBL + sw1) = l1;
            s += __shfl_xor_sync(0xffffffffu, s, 1);
            s += __shfl_xor_sync(0xffffffffu, s, 2);
            if (sub == 0) {
                l_run[row] = l_run[row] * fac + s;
                m_run[row] = mnew;
                fsc[row] = fac;
            }
        }
        __syncthreads();

        // ---- O rescale + PV (3 chains) ----
        {
            const float f0 = fsc[mwq + er], f1 = fsc[mwq + er + 8];
#pragma unroll
            for (int j = 0; j < 4; j++) {
                accO[j][0] *= f0; accO[j][1] *= f0;
                accO[j][2] *= f1; accO[j][3] *= f1;
            }
#pragma unroll
            for (int ks = 0; ks < 4; ks++) {
                const int cb = ks << 5;
                uint32_t pah[4], pal[4], vf[2][4];
                ldsm4(pah, sb + AT_PBH + SMEM_SWIZZLE_128B(
                    (uint32_t)((mwq + aRow) * 128 + cb + aCol)));
                ldsm4(pal, sb + AT_PBL + SMEM_SWIZZLE_128B(
                    (uint32_t)((mwq + aRow) * 128 + cb + aCol)));
#pragma unroll
                for (int p = 0; p < 2; p++)
                    ldsm4(vf[p], bufb + 16384 + SMEM_SWIZZLE_128B(
                        (uint32_t)((ng * 32 + p * 16 + bRow) * 128 + cb + bCol)));
#pragma unroll
                for (int j = 0; j < 4; j++)
                    mma16816(accO[j], pah, &vf[j >> 1][(j & 1) * 2]);
#pragma unroll
                for (int j = 0; j < 4; j++)
                    mma16816(accO[j], pal, &vf[j >> 1][(j & 1) * 2]);
#pragma unroll
                for (int p = 0; p < 2; p++)
                    ldsm4(vf[p], bufb + 24576 + SMEM_SWIZZLE_128B(
                        (uint32_t)((ng * 32 + p * 16 + bRow) * 128 + cb + bCol)));
#pragma unroll
                for (int j = 0; j < 4; j++)
                    mma16816(accO[j], pah, &vf[j >> 1][(j & 1) * 2]);
            }
        }
    }

    // finalize: out[hb, q, hn*64 + d] = O / l
    {
        const float inv0 = 1.0f / l_run[mwq + er];
        const float inv1 = 1.0f / l_run[mwq + er + 8];
        const int r0 = q0 + mwq + er;
#pragma unroll
        for (int j = 0; j < 4; j++) {
            const int col = hn * 64 + ng * 32 + j * 8 + ec;
            *(float2*)&out[(size_t)(hb * LL + r0) * DM + col] =
                make_float2(accO[j][0] * inv0, accO[j][1] * inv0);
            *(float2*)&out[(size_t)(hb * LL + r0 + 8) * DM + col] =
                make_float2(accO[j][2] * inv1, accO[j][3] * inv1);
        }
    }
}

// ============================================================
extern "C" void kernel_launch(void* const* d_in, const int* in_sizes, int n_in,
                              void* d_out, int out_size) {
    const float* x   = (const float*)d_in[0];
    const float* pos = (const float*)d_in[1];
    const float* W   = (const float*)d_in[2];
    const float* bqk = (const float*)d_in[3];
    const float* rr  = (const float*)d_in[4];
    const float* rw  = (const float*)d_in[5];
    float* out = (float*)d_out;

    cudaFuncSetAttribute(qkv_tc_kernel,
                         cudaFuncAttributeMaxDynamicSharedMemorySize, QK_SMEM_TOTAL);
    cudaFuncSetAttribute(attn_tc_kernel,
                         cudaFuncAttributeMaxDynamicSharedMemorySize, AT_SMEM);

    conv_x_kernel<<<(MROWS * DM) / 256, 256>>>(x);
    conv_w_kernel<<<dim3(NCOLS / 32, DM / 32), dim3(32, 8)>>>(W);
    pos_split_kernel<<<(2 * LL * DHEAD) / 256, 256>>>(pos);
    qkv_tc_kernel<<<NSM, 256, QK_SMEM_TOTAL>>>(bqk);
    splitv_kernel<<<dim3(LL / 64, BB * NHEAD), 256>>>(rr, rw);
    attn_tc_kernel<<<dim3(LL / 64, NHEAD, BB), 256, AT_SMEM>>>(out);
}